// round 1
// baseline (speedup 1.0000x reference)
#include <cuda_runtime.h>
#include <math.h>

#define BB 32
#define NN 512
#define DD 256
#define HH 8
#define HD 32
#define LWW 25
#define NQ 2048

// ---------------- scratch (device globals; no allocation) ----------------
__device__ float g_M[BB*NN*DD];
__device__ float g_E[BB*NN*DD];
__device__ float g_Sbase[BB*NN*DD];
__device__ float g_Slocal[BB*NN*DD];
__device__ float g_Ssg[BB*NN*DD];
__device__ float g_Sglob[BB*NN*DD];
__device__ float g_Sbl[BB*NN*DD];
__device__ float g_Ssgl[BB*NN*DD];
__device__ float g_Q[BB*NN*DD];
__device__ float g_K[BB*NN*DD];
__device__ float g_V[BB*NN*DD];
__device__ float g_Oh[BB*NN*DD];
__device__ float g_T[BB*NN*DD];
__device__ float g_SW[NQ*NQ];          // softmaxed skill_cluster_weights
__device__ float g_srep[NQ*DD];        // skill repr for all 2048 rows
__device__ float g_sgr[BB*NN*DD];      // gathered skill_group_repr
__device__ float g_sg1[BB*NN*NN];      // S_sg einsum result
__device__ float g_sg2[BB*NN*DD];      // after skill_to_embed
__device__ float g_scores[BB*HH*NN*NN];
__device__ float g_loc[BB*LWW*DD];
__device__ float g_locout[BB*LWW*DD];
__device__ float g_sum[BB*NN*DD];
__device__ float g_f1[BB*NN*DD];
__device__ float g_f2[BB*NN*DD];
__device__ float g_F[BB*NN*DD];

// ---------------- kernels ----------------

// Y[M,Nout] = X[M,K] @ W[Nout,K]^T + bias ; act: 0 none, 1 relu
__global__ void linear_kernel(const float* __restrict__ X,
                              const float* __restrict__ W,
                              const float* __restrict__ bias,
                              float* __restrict__ Y,
                              int M, int K, int Nout, int act)
{
    const int BM=64, BN=64, BK=16;
    __shared__ float As[BK][BM+1];
    __shared__ float Bs[BK][BN+1];
    int m0 = blockIdx.y * BM;
    int n0 = blockIdx.x * BN;
    int t = threadIdx.x;
    int tx = t & 15, ty = t >> 4;
    float acc[4][4] = {};
    for (int k0 = 0; k0 < K; k0 += BK) {
        #pragma unroll
        for (int i = 0; i < 4; i++) {
            int idx = t + i*256;
            int r = idx / BK, c = idx % BK;
            int gm = m0 + r, gn = n0 + r, gk = k0 + c;
            As[c][r] = (gm < M)    ? X[(size_t)gm*K + gk] : 0.f;
            Bs[c][r] = (gn < Nout) ? W[(size_t)gn*K + gk] : 0.f;
        }
        __syncthreads();
        #pragma unroll
        for (int k = 0; k < BK; k++) {
            float a[4], b[4];
            #pragma unroll
            for (int i=0;i<4;i++) a[i] = As[k][ty*4+i];
            #pragma unroll
            for (int j=0;j<4;j++) b[j] = Bs[k][tx*4+j];
            #pragma unroll
            for (int i=0;i<4;i++)
                #pragma unroll
                for (int j=0;j<4;j++)
                    acc[i][j] = fmaf(a[i], b[j], acc[i][j]);
        }
        __syncthreads();
    }
    #pragma unroll
    for (int i=0;i<4;i++){
        int gm = m0 + ty*4 + i;
        if (gm >= M) continue;
        #pragma unroll
        for (int j=0;j<4;j++){
            int gn = n0 + tx*4 + j;
            if (gn >= Nout) continue;
            float v = acc[i][j] + (bias ? bias[gn] : 0.f);
            if (act==1) v = fmaxf(v, 0.f);
            Y[(size_t)gm*Nout + gn] = v;
        }
    }
}

// scores[bh, i, j] = (Q[b,i,h,:] . K[b,j,h,:]) / sqrt(32), masked
__global__ void scores_kernel(const float* __restrict__ Q, const float* __restrict__ K,
                              float* __restrict__ S, int Lq, int Lk, int causal)
{
    int bh = blockIdx.z;
    int b = bh / HH, h = bh % HH;
    int i0 = blockIdx.y * 32, j0 = blockIdx.x * 32;
    __shared__ float Qs[32][33], Ks[32][33];
    int t = threadIdx.x;
    int r = t >> 3, c4 = (t & 7) * 4;
    #pragma unroll
    for (int k=0;k<4;k++){
        int gi = i0 + r, gj = j0 + r;
        Qs[r][c4+k] = (gi < Lq) ? Q[((size_t)(b*Lq + gi))*DD + h*HD + c4 + k] : 0.f;
        Ks[r][c4+k] = (gj < Lk) ? K[((size_t)(b*Lk + gj))*DD + h*HD + c4 + k] : 0.f;
    }
    __syncthreads();
    int i = r, j4 = c4;
    float acc[4] = {0,0,0,0};
    #pragma unroll
    for (int c=0;c<HD;c++){
        float qv = Qs[i][c];
        #pragma unroll
        for (int jj=0;jj<4;jj++) acc[jj] = fmaf(qv, Ks[j4+jj][c], acc[jj]);
    }
    const float scale = 0.1767766953f; // 1/sqrt(32)
    int gi = i0 + i;
    if (gi < Lq) {
        #pragma unroll
        for (int jj=0;jj<4;jj++){
            int gj = j0 + j4 + jj;
            if (gj < Lk) {
                float v = acc[jj] * scale;
                if (causal && gj > gi) v = -1e9f;
                S[(((size_t)bh)*Lq + gi)*Lk + gj] = v;
            }
        }
    }
}

// row softmax: one block per row, up to 2048 elems
__global__ void softmax_kernel(const float* __restrict__ src, float* __restrict__ dst, int L)
{
    size_t row = blockIdx.x;
    const float* p = src + row * (size_t)L;
    float* o = dst + row * (size_t)L;
    int t = threadIdx.x;
    float vals[8];
    int cnt = (L + 255) / 256;
    float mx = -1e30f;
    for (int i=0;i<cnt;i++){
        int idx = t + i*256;
        vals[i] = (idx < L) ? p[idx] : -1e30f;
        mx = fmaxf(mx, vals[i]);
    }
    __shared__ float red[256];
    red[t] = mx; __syncthreads();
    for (int s=128;s>0;s>>=1){ if (t<s) red[t]=fmaxf(red[t],red[t+s]); __syncthreads(); }
    mx = red[0]; __syncthreads();
    float sum = 0.f;
    for (int i=0;i<cnt;i++){
        int idx = t + i*256;
        if (idx < L){ vals[i] = expf(vals[i]-mx); sum += vals[i]; }
    }
    red[t]=sum; __syncthreads();
    for (int s=128;s>0;s>>=1){ if (t<s) red[t]+=red[t+s]; __syncthreads(); }
    float inv = 1.f/red[0];
    for (int i=0;i<cnt;i++){
        int idx = t + i*256;
        if (idx < L) o[idx] = vals[i]*inv;
    }
}

// head-mean of attn0 weights -> output
__global__ void attn_mean_kernel(const float* __restrict__ S, float* __restrict__ out)
{
    size_t idx = (size_t)blockIdx.x*256 + threadIdx.x;
    size_t per_b = (size_t)NN*NN;
    if (idx >= (size_t)BB*per_b) return;
    size_t b = idx / per_b;
    size_t rem = idx % per_b;
    float s = 0.f;
    #pragma unroll
    for (int h=0;h<HH;h++)
        s += S[((size_t)(b*HH+h))*per_b + rem];
    out[idx] = s * 0.125f;
}

// O[b,i,h*32+c] = sum_j S[bh,i,j] * V[b,j,h*32+c]
__global__ void av_kernel(const float* __restrict__ S, const float* __restrict__ V,
                          float* __restrict__ O, int Lq, int Lk)
{
    int bh = blockIdx.y;
    int b = bh / HH, h = bh % HH;
    int i0 = blockIdx.x * 32;
    int t = threadIdx.x;
    int r = t >> 3, c4 = (t & 7) * 4;
    float acc[4]={0,0,0,0};
    __shared__ float Ss[32][33], Vs[32][33];
    for (int j0 = 0; j0 < Lk; j0 += 32) {
        #pragma unroll
        for (int k=0;k<4;k++){
            int gi = i0 + r, gj = j0 + c4 + k;
            Ss[r][c4+k] = (gi < Lq && gj < Lk) ? S[(((size_t)bh)*Lq+gi)*Lk+gj] : 0.f;
            int gjr = j0 + r;
            Vs[r][c4+k] = (gjr < Lk) ? V[((size_t)(b*Lk+gjr))*DD + h*HD + c4 + k] : 0.f;
        }
        __syncthreads();
        #pragma unroll
        for (int j=0;j<32;j++){
            float s = Ss[r][j];
            #pragma unroll
            for (int k=0;k<4;k++) acc[k] = fmaf(s, Vs[j][c4+k], acc[k]);
        }
        __syncthreads();
    }
    int gi = i0 + r;
    if (gi < Lq){
        #pragma unroll
        for (int k=0;k<4;k++)
            O[((size_t)(b*Lq+gi))*DD + h*HD + c4 + k] = acc[k];
    }
}

// Out[b,n,m] = sum_d X[b,n,d] * Y[b,m,d]
__global__ void abT_kernel(const float* __restrict__ X, const float* __restrict__ Y,
                           float* __restrict__ Out, int M1, int M2, int Kd)
{
    int b = blockIdx.z;
    int i0 = blockIdx.y*32, j0 = blockIdx.x*32;
    __shared__ float Xs[32][33], Ys[32][33];
    int t = threadIdx.x;
    int r = t >> 3, c4 = (t & 7) * 4;
    float acc[4]={0,0,0,0};
    for (int k0=0;k0<Kd;k0+=32){
        #pragma unroll
        for (int k=0;k<4;k++){
            int gi = i0+r, gj = j0+r;
            Xs[r][c4+k] = (gi<M1) ? X[((size_t)(b*M1+gi))*Kd + k0+c4+k] : 0.f;
            Ys[r][c4+k] = (gj<M2) ? Y[((size_t)(b*M2+gj))*Kd + k0+c4+k] : 0.f;
        }
        __syncthreads();
        #pragma unroll
        for (int c=0;c<32;c++){
            float xv = Xs[r][c];
            #pragma unroll
            for (int jj=0;jj<4;jj++) acc[jj] = fmaf(xv, Ys[c4+jj][c], acc[jj]);
        }
        __syncthreads();
    }
    int gi=i0+r;
    if (gi<M1){
        #pragma unroll
        for (int jj=0;jj<4;jj++){
            int gj=j0+c4+jj;
            if (gj<M2) Out[((size_t)(b*M1+gi))*M2+gj]=acc[jj];
        }
    }
}

// out = LN(a + b (+ c)) * g + beta ; one block (256 thr) per row of D=256
__global__ void add_ln_kernel(const float* __restrict__ a, const float* __restrict__ b,
                              const float* __restrict__ c,
                              const float* __restrict__ g, const float* __restrict__ bet,
                              float* __restrict__ out)
{
    size_t row = blockIdx.x;
    int t = threadIdx.x;
    float x = a[row*DD+t] + b[row*DD+t];
    if (c) x += c[row*DD+t];
    __shared__ float red[256];
    red[t]=x; __syncthreads();
    for (int s=128;s>0;s>>=1){ if(t<s) red[t]+=red[t+s]; __syncthreads(); }
    float mean = red[0]*(1.f/DD); __syncthreads();
    float d = x-mean;
    red[t]=d*d; __syncthreads();
    for (int s=128;s>0;s>>=1){ if(t<s) red[t]+=red[t+s]; __syncthreads(); }
    float var = red[0]*(1.f/DD);
    out[row*DD+t] = d * rsqrtf(var+1e-5f) * g[t] + bet[t];
}

__global__ void embed_kernel(const int* __restrict__ q, const int* __restrict__ r,
                             const int* __restrict__ qry,
                             const float* __restrict__ M_emb, const float* __restrict__ E_emb,
                             const float* __restrict__ P,
                             float* __restrict__ M, float* __restrict__ E)
{
    int row = blockIdx.x; int t = threadIdx.x;
    int n = row % NN;
    int x = q[row] + NQ * r[row];
    M[(size_t)row*DD + t] = M_emb[(size_t)x*DD + t] + P[n*DD + t];
    E[(size_t)row*DD + t] = E_emb[(size_t)qry[row]*DD + t];
}

__global__ void gather_skill_kernel(const int* __restrict__ q, const float* __restrict__ rep,
                                    float* __restrict__ out)
{
    int row = blockIdx.x; int t = threadIdx.x;
    out[(size_t)row*DD+t] = rep[(size_t)q[row]*DD+t];
}

__global__ void gather_loc_kernel(const float* __restrict__ Sb, float* __restrict__ loc)
{
    int row = blockIdx.x; int t = threadIdx.x;  // row in [0, B*LW)
    int b = row / LWW, j = row % LWW;
    loc[(size_t)row*DD+t] = Sb[((size_t)(b*NN + NN-LWW + j))*DD + t];
}

__global__ void scatter_loc_kernel(const float* __restrict__ locout, float* __restrict__ Sl)
{
    int row = blockIdx.x; int t = threadIdx.x;
    int b = row / LWW, j = row % LWW;
    Sl[((size_t)(b*NN + NN-LWW + j))*DD + t] = locout[(size_t)row*DD+t];
}

__global__ void fill_zero_kernel(float* __restrict__ p, size_t n)
{
    size_t i = (size_t)blockIdx.x*256 + threadIdx.x;
    if (i < n) p[i] = 0.f;
}

__global__ void sum6_kernel(const float* a, const float* b, const float* c,
                            const float* d, const float* e, const float* f,
                            float* __restrict__ out, size_t n)
{
    size_t i = (size_t)blockIdx.x*256 + threadIdx.x;
    if (i < n) out[i] = a[i]+b[i]+c[i]+d[i]+e[i]+f[i];
}

__global__ void pred_kernel(const float* __restrict__ F, const float* __restrict__ w,
                            const float* __restrict__ b, float* __restrict__ out)
{
    size_t row = blockIdx.x;
    int t = threadIdx.x;
    float v = F[row*DD+t]*w[t];
    __shared__ float red[256];
    red[t]=v; __syncthreads();
    for (int s=128;s>0;s>>=1){ if(t<s) red[t]+=red[t+s]; __syncthreads(); }
    if (t==0) out[row] = 1.f/(1.f+expf(-(red[0]+b[0])));
}

// ---------------- host orchestration ----------------

static void run_linear(const float* X, const float* W, const float* bias, float* Y,
                       int M, int K, int Nout, int act)
{
    dim3 g((Nout+63)/64, (M+63)/64);
    linear_kernel<<<g,256>>>(X, W, bias, Y, M, K, Nout, act);
}

static void run_mha(const float* qin, const float* kin, const float* vin,
                    const float* in_w, const float* in_b,
                    const float* out_w, const float* out_b,
                    int Lq, int Lk, int causal,
                    float* Qb, float* Kb, float* Vb, float* Sc, float* Ohb,
                    float* out, float* attn_mean)
{
    run_linear(qin, in_w,            in_b,        Qb, BB*Lq, DD, DD, 0);
    run_linear(kin, in_w + DD*DD,    in_b + DD,   Kb, BB*Lk, DD, DD, 0);
    run_linear(vin, in_w + 2*DD*DD,  in_b + 2*DD, Vb, BB*Lk, DD, DD, 0);
    dim3 g1((Lk+31)/32, (Lq+31)/32, BB*HH);
    scores_kernel<<<g1,256>>>(Qb, Kb, Sc, Lq, Lk, causal);
    softmax_kernel<<<BB*HH*Lq,256>>>(Sc, Sc, Lk);
    if (attn_mean)
        attn_mean_kernel<<<(unsigned)(((size_t)BB*NN*NN+255)/256),256>>>(Sc, attn_mean);
    dim3 g2((Lq+31)/32, BB*HH);
    av_kernel<<<g2,256>>>(Sc, Vb, Ohb, Lq, Lk);
    run_linear(Ohb, out_w, out_b, out, BB*Lq, DD, DD, 0);
}

#define GETSYM(var, symbol) float* var; { void* _p=nullptr; cudaGetSymbolAddress(&_p, symbol); var=(float*)_p; }

extern "C" void kernel_launch(void* const* d_in, const int* in_sizes, int n_in,
                              void* d_out, int out_size)
{
    const int*   q    = (const int*)d_in[0];
    const int*   r    = (const int*)d_in[1];
    const int*   qry  = (const int*)d_in[2];
    const float* M_emb = (const float*)d_in[3];
    const float* E_emb = (const float*)d_in[4];
    const float* P     = (const float*)d_in[5];
    const float* attn_in_w  = (const float*)d_in[6];
    const float* attn_in_b  = (const float*)d_in[7];
    const float* attn_out_w = (const float*)d_in[8];
    const float* attn_out_b = (const float*)d_in[9];
    const float* skill_cw   = (const float*)d_in[10];
    const float* skill_pw   = (const float*)d_in[11];
    const float* skill_pb   = (const float*)d_in[12];
    const float* skill_ew   = (const float*)d_in[13];
    const float* skill_eb   = (const float*)d_in[14];
    const float* ffn_w1 = (const float*)d_in[15];
    const float* ffn_b1 = (const float*)d_in[16];
    const float* ffn_w2 = (const float*)d_in[17];
    const float* ffn_b2 = (const float*)d_in[18];
    const float* ln1_g  = (const float*)d_in[19];
    const float* ln1_b  = (const float*)d_in[20];
    const float* ln2_g  = (const float*)d_in[21];
    const float* ln2_b  = (const float*)d_in[22];
    const float* pred_w = (const float*)d_in[23];
    const float* pred_b = (const float*)d_in[24];

    float* out_p = (float*)d_out;                 // (B, N)
    float* out_attn = out_p + BB*NN;              // (B, N, N)

    GETSYM(pM, g_M);   GETSYM(pE, g_E);   GETSYM(pSbase, g_Sbase); GETSYM(pSlocal, g_Slocal);
    GETSYM(pSsg, g_Ssg); GETSYM(pSglob, g_Sglob); GETSYM(pSbl, g_Sbl); GETSYM(pSsgl, g_Ssgl);
    GETSYM(pQ, g_Q);   GETSYM(pK, g_K);   GETSYM(pV, g_V);   GETSYM(pOh, g_Oh); GETSYM(pT, g_T);
    GETSYM(pSW, g_SW); GETSYM(psrep, g_srep); GETSYM(psgr, g_sgr);
    GETSYM(psg1, g_sg1); GETSYM(psg2, g_sg2); GETSYM(pSc, g_scores);
    GETSYM(ploc, g_loc); GETSYM(plocout, g_locout);
    GETSYM(psum, g_sum); GETSYM(pf1, g_f1); GETSYM(pf2, g_f2); GETSYM(pF, g_F);

    const size_t BND = (size_t)BB*NN*DD;

    // 1. embeddings
    embed_kernel<<<BB*NN,256>>>(q, r, qry, M_emb, E_emb, P, pM, pE);

    // 2. attn0: E attends to M, causal, with head-mean weights output
    run_mha(pE, pM, pM,
            attn_in_w + 0, attn_in_b + 0, attn_out_w + 0, attn_out_b + 0,
            NN, NN, 1, pQ, pK, pV, pSc, pOh, pT, out_attn);

    // 3. S_base = LN(attn0 + M + E)
    add_ln_kernel<<<BB*NN,256>>>(pT, pM, pE, ln1_g, ln1_b, pSbase);

    // 4. local attention on last LW rows
    gather_loc_kernel<<<BB*LWW,256>>>(pSbase, ploc);
    run_mha(ploc, ploc, ploc,
            attn_in_w + 1*3*DD*DD, attn_in_b + 1*3*DD, attn_out_w + 1*DD*DD, attn_out_b + 1*DD,
            LWW, LWW, 1, pQ, pK, pV, pSc, pOh, plocout, nullptr);
    fill_zero_kernel<<<(unsigned)((BND+255)/256),256>>>(pSlocal, BND);
    scatter_loc_kernel<<<BB*LWW,256>>>(plocout, pSlocal);

    // 5. skill path: softmax rows once over all 2048 rows, project, gather
    softmax_kernel<<<NQ,256>>>(skill_cw, pSW, NQ);
    run_linear(pSW, skill_pw, skill_pb, psrep, NQ, NQ, DD, 0);
    gather_skill_kernel<<<BB*NN,256>>>(q, psrep, psgr);

    // 6. S_sg1[b,n,m] = S_base . skill_group_repr
    {
        dim3 g(NN/32, NN/32, BB);
        abT_kernel<<<g,256>>>(pSbase, psgr, psg1, NN, NN, DD);
    }
    // 7. S_sg2 = S_sg1 @ skill_to_embed_w^T + b   (K = N = 512)
    run_linear(psg1, skill_ew, skill_eb, psg2, BB*NN, NN, DD, 0);

    // 8. attn2 (self, no mask) on S_sg2 -> pSsg
    run_mha(psg2, psg2, psg2,
            attn_in_w + 2*3*DD*DD, attn_in_b + 2*3*DD, attn_out_w + 2*DD*DD, attn_out_b + 2*DD,
            NN, NN, 0, pQ, pK, pV, pSc, pOh, pSsg, nullptr);

    // 9. attn3 (self, causal) on S_base -> pSglob
    run_mha(pSbase, pSbase, pSbase,
            attn_in_w + 3*3*DD*DD, attn_in_b + 3*3*DD, attn_out_w + 3*DD*DD, attn_out_b + 3*DD,
            NN, NN, 1, pQ, pK, pV, pSc, pOh, pSglob, nullptr);

    // 10. attn4: q=S_base, kv=S_local, no mask -> pSbl
    run_mha(pSbase, pSlocal, pSlocal,
            attn_in_w + 4*3*DD*DD, attn_in_b + 4*3*DD, attn_out_w + 4*DD*DD, attn_out_b + 4*DD,
            NN, NN, 0, pQ, pK, pV, pSc, pOh, pSbl, nullptr);

    // 11. attn5: q=S_sg, kv=S_glob, no mask -> pSsgl
    run_mha(pSsg, pSglob, pSglob,
            attn_in_w + 5*3*DD*DD, attn_in_b + 5*3*DD, attn_out_w + 5*DD*DD, attn_out_b + 5*DD,
            NN, NN, 0, pQ, pK, pV, pSc, pOh, pSsgl, nullptr);

    // 12. S = sum of six streams
    sum6_kernel<<<(unsigned)((BND+255)/256),256>>>(pSbase, pSlocal, pSsg, pSglob, pSbl, pSsgl,
                                                   psum, BND);

    // 13. FFN + residual + LN2
    run_linear(psum, ffn_w1, ffn_b1, pf1, BB*NN, DD, DD, 1);
    run_linear(pf1,  ffn_w2, ffn_b2, pf2, BB*NN, DD, DD, 0);
    add_ln_kernel<<<BB*NN,256>>>(pf2, psum, nullptr, ln2_g, ln2_b, pF);

    // 14. prediction head
    pred_kernel<<<BB*NN,256>>>(pF, pred_w, pred_b, out_p);
}

// round 2
// speedup vs baseline: 1.3327x; 1.3327x over previous
#include <cuda_runtime.h>
#include <math.h>

#define BB 32
#define NN 512
#define DD 256
#define HH 8
#define HD 32
#define LWW 25
#define NQ 2048

// ---------------- scratch (device globals; no allocation) ----------------
__device__ float g_M[BB*NN*DD];
__device__ float g_E[BB*NN*DD];
__device__ float g_Sbase[BB*NN*DD];
__device__ float g_Slocal[BB*NN*DD];
__device__ float g_Ssg[BB*NN*DD];
__device__ float g_Sglob[BB*NN*DD];
__device__ float g_Sbl[BB*NN*DD];
__device__ float g_Ssgl[BB*NN*DD];
__device__ float g_QKV[BB*NN*3*DD];   // fused qkv projections (stride 768)
__device__ float g_Qb[BB*NN*DD];      // separate q proj (stride 256)
__device__ float g_KV[BB*NN*2*DD];    // separate kv proj (stride 512)
__device__ float g_Oh[BB*NN*DD];
__device__ float g_T[BB*NN*DD];
__device__ float g_SW[NQ*NQ];
__device__ float g_srep[NQ*DD];
__device__ float g_sgr[BB*NN*DD];
__device__ float g_sg1[BB*NN*NN];
__device__ float g_sg2[BB*NN*DD];
__device__ float g_loc[BB*LWW*DD];
__device__ float g_locout[BB*LWW*DD];
__device__ float g_sum[BB*NN*DD];
__device__ float g_f1[BB*NN*DD];
__device__ float g_F[BB*NN*DD];

// ---------------- FFMA2 helper ----------------
typedef unsigned long long ull;
#define FFMA2(d, a, b) asm("fma.rn.f32x2 %0, %1, %2, %3;" : "=l"(d) : "l"(a), "l"(b), "l"(d))

// ---------------- GEMM: Y[M,N] = X[M,K] @ W[N,K]^T + bias, optional relu, batched ----------------
// 128x128x16 tiles, 8x8 per thread, packed f32x2 FMA.
__global__ __launch_bounds__(256) void gemm128_kernel(
    const float* __restrict__ X, const float* __restrict__ W,
    const float* __restrict__ bias, float* __restrict__ Y,
    int M, int K, int Nout, int act,
    long sX, long sW, long sY)
{
    X += (size_t)blockIdx.z * sX;
    W += (size_t)blockIdx.z * sW;
    Y += (size_t)blockIdx.z * sY;

    __shared__ float As2[16][256];   // A duplicated: As2[k][2r]=As2[k][2r+1]=X[m0+r][k]
    __shared__ float Bs[16][128];

    int t = threadIdx.x;
    int tx = t & 15, ty = t >> 4;
    int m0 = blockIdx.y * 128, n0 = blockIdx.x * 128;

    ull acc[8][4];
    #pragma unroll
    for (int i = 0; i < 8; i++)
        #pragma unroll
        for (int j = 0; j < 4; j++) acc[i][j] = 0ull;

    for (int k0 = 0; k0 < K; k0 += 16) {
        #pragma unroll
        for (int l = 0; l < 2; l++) {
            int id = t + l * 256;
            int r = id >> 2, c = (id & 3) * 4;
            int gm = m0 + r;
            float4 v = make_float4(0.f, 0.f, 0.f, 0.f);
            if (gm < M) v = *(const float4*)&X[(size_t)gm * K + k0 + c];
            *(float2*)&As2[c + 0][2 * r] = make_float2(v.x, v.x);
            *(float2*)&As2[c + 1][2 * r] = make_float2(v.y, v.y);
            *(float2*)&As2[c + 2][2 * r] = make_float2(v.z, v.z);
            *(float2*)&As2[c + 3][2 * r] = make_float2(v.w, v.w);
            int gn = n0 + r;
            float4 w = make_float4(0.f, 0.f, 0.f, 0.f);
            if (gn < Nout) w = *(const float4*)&W[(size_t)gn * K + k0 + c];
            Bs[c + 0][r] = w.x; Bs[c + 1][r] = w.y; Bs[c + 2][r] = w.z; Bs[c + 3][r] = w.w;
        }
        __syncthreads();
        #pragma unroll
        for (int k = 0; k < 16; k++) {
            ull a2[8];
            #pragma unroll
            for (int i = 0; i < 8; i++)
                a2[i] = *(const ull*)&As2[k][2 * (ty * 8 + i)];
            ull b2[4];
            float4 bA = *(const float4*)&Bs[k][tx * 8];
            float4 bB = *(const float4*)&Bs[k][tx * 8 + 4];
            b2[0] = ((const ull*)&bA)[0]; b2[1] = ((const ull*)&bA)[1];
            b2[2] = ((const ull*)&bB)[0]; b2[3] = ((const ull*)&bB)[1];
            #pragma unroll
            for (int i = 0; i < 8; i++)
                #pragma unroll
                for (int j = 0; j < 4; j++)
                    FFMA2(acc[i][j], a2[i], b2[j]);
        }
        __syncthreads();
    }

    #pragma unroll
    for (int i = 0; i < 8; i++) {
        int gm = m0 + ty * 8 + i;
        if (gm >= M) continue;
        float res[8];
        #pragma unroll
        for (int j = 0; j < 4; j++) {
            float2 p = *(float2*)&acc[i][j];
            res[2 * j] = p.x; res[2 * j + 1] = p.y;
        }
        #pragma unroll
        for (int j = 0; j < 8; j++) {
            int gn = n0 + tx * 8 + j;
            if (gn >= Nout) continue;
            float v = res[j] + (bias ? bias[gn] : 0.f);
            if (act == 1) v = fmaxf(v, 0.f);
            Y[(size_t)gm * Nout + gn] = v;
        }
    }
}

// ---------------- fused attention ----------------
// grid: (ceil(Lq/32), B), block 256. Loops heads. Dynamic smem:
// Qst[32][36] (transposed) | KV (max(32*132, 128*36)=4608) | rowinv[32] | sc[32][LKP] | wacc[32][LKP]?
__global__ __launch_bounds__(256) void attn_fused(
    const float* __restrict__ Qm, int sQ,
    const float* __restrict__ Km, const float* __restrict__ Vm, int sKV,
    float* __restrict__ O, float* __restrict__ wmean,
    int Lq, int Lk, int NC, int causal)
{
    extern __shared__ float sm[];
    float* Qst = sm;                         // [k][r] : k*36 + r
    float* KV  = sm + 32 * 36;               // scores: [k][j] k*132+j ; AV: [j][c] j*36+c
    float* rowinv = KV + 128 * 36;
    int LKP = NC * 128 + 1;
    float* sc = rowinv + 32;
    float* wacc = sc + 32 * LKP;

    int b = blockIdx.y;
    int i0 = blockIdx.x * 32;
    int t = threadIdx.x;
    const float scale = 0.1767766953f; // 1/sqrt(32)

    for (int h = 0; h < HH; h++) {
        // load Q tile (transposed)
        {
            int r = t >> 3, k4 = (t & 7) * 4;
            int gi = i0 + r;
            float4 v = make_float4(0.f, 0.f, 0.f, 0.f);
            if (gi < Lq) v = *(const float4*)&Qm[(size_t)(b * Lq + gi) * sQ + h * HD + k4];
            Qst[(k4 + 0) * 36 + r] = v.x;
            Qst[(k4 + 1) * 36 + r] = v.y;
            Qst[(k4 + 2) * 36 + r] = v.z;
            Qst[(k4 + 3) * 36 + r] = v.w;
        }
        // ---- scores ----
        for (int jc = 0; jc < NC; jc++) {
            __syncthreads();
            #pragma unroll
            for (int l = 0; l < 4; l++) {
                int id = t + l * 256;
                int jl = id >> 3, k4 = (id & 7) * 4;
                int gj = jc * 128 + jl;
                float4 v = make_float4(0.f, 0.f, 0.f, 0.f);
                if (gj < Lk) v = *(const float4*)&Km[(size_t)(b * Lk + gj) * sKV + h * HD + k4];
                KV[(k4 + 0) * 132 + jl] = v.x;
                KV[(k4 + 1) * 132 + jl] = v.y;
                KV[(k4 + 2) * 132 + jl] = v.z;
                KV[(k4 + 3) * 132 + jl] = v.w;
            }
            __syncthreads();
            int ri = (t >> 5) * 4;
            int cj = (t & 31) * 4;
            float acc[4][4] = {};
            #pragma unroll
            for (int k = 0; k < HD; k++) {
                float4 a = *(const float4*)&Qst[k * 36 + ri];
                float4 bv = *(const float4*)&KV[k * 132 + cj];
                float av[4] = {a.x, a.y, a.z, a.w};
                float bw[4] = {bv.x, bv.y, bv.z, bv.w};
                #pragma unroll
                for (int u = 0; u < 4; u++)
                    #pragma unroll
                    for (int v2 = 0; v2 < 4; v2++)
                        acc[u][v2] = fmaf(av[u], bw[v2], acc[u][v2]);
            }
            #pragma unroll
            for (int u = 0; u < 4; u++) {
                int gi = i0 + ri + u;
                #pragma unroll
                for (int v2 = 0; v2 < 4; v2++) {
                    int col = jc * 128 + cj + v2;
                    float s = acc[u][v2] * scale;
                    if (col >= Lk || (causal && col > gi)) s = -1e30f;
                    sc[(ri + u) * LKP + col] = s;
                }
            }
        }
        __syncthreads();
        // ---- softmax (8 lanes per row) ----
        {
            int row = t >> 3, lane = t & 7;
            int L = NC * 128;
            float mx = -1e30f;
            for (int c = lane; c < L; c += 8) mx = fmaxf(mx, sc[row * LKP + c]);
            #pragma unroll
            for (int o = 4; o; o >>= 1) mx = fmaxf(mx, __shfl_xor_sync(0xffffffffu, mx, o));
            float sum = 0.f;
            for (int c = lane; c < L; c += 8) {
                float e = __expf(sc[row * LKP + c] - mx);
                sc[row * LKP + c] = e;
                sum += e;
            }
            #pragma unroll
            for (int o = 4; o; o >>= 1) sum += __shfl_xor_sync(0xffffffffu, sum, o);
            float inv = 1.f / sum;
            if (lane == 0) rowinv[row] = inv;
            if (wmean) {
                if (h == 0)
                    for (int c = lane; c < L; c += 8) wacc[row * LKP + c] = sc[row * LKP + c] * inv;
                else
                    for (int c = lane; c < L; c += 8) wacc[row * LKP + c] += sc[row * LKP + c] * inv;
            }
        }
        // ---- AV ----
        int r = t >> 3, c4 = (t & 7) * 4;
        float oa0 = 0.f, oa1 = 0.f, oa2 = 0.f, oa3 = 0.f;
        for (int jc = 0; jc < NC; jc++) {
            __syncthreads();
            #pragma unroll
            for (int l = 0; l < 4; l++) {
                int id = t + l * 256;
                int jl = id >> 3, cc4 = (id & 7) * 4;
                int gj = jc * 128 + jl;
                float4 v = make_float4(0.f, 0.f, 0.f, 0.f);
                if (gj < Lk) v = *(const float4*)&Vm[(size_t)(b * Lk + gj) * sKV + h * HD + cc4];
                *(float4*)&KV[jl * 36 + cc4] = v;
            }
            __syncthreads();
            const float* srow = &sc[r * LKP + jc * 128];
            #pragma unroll 4
            for (int jl = 0; jl < 128; jl++) {
                float s = srow[jl];
                float4 v = *(const float4*)&KV[jl * 36 + c4];
                oa0 = fmaf(s, v.x, oa0);
                oa1 = fmaf(s, v.y, oa1);
                oa2 = fmaf(s, v.z, oa2);
                oa3 = fmaf(s, v.w, oa3);
            }
        }
        {
            float inv = rowinv[r];
            int gi = i0 + r;
            if (gi < Lq) {
                float4 ov = make_float4(oa0 * inv, oa1 * inv, oa2 * inv, oa3 * inv);
                *(float4*)&O[(size_t)(b * Lq + gi) * DD + h * HD + c4] = ov;
            }
        }
        __syncthreads();
    }
    if (wmean) {
        for (int rr = 0; rr < 32; rr++) {
            int gi = i0 + rr;
            if (gi >= Lq) continue;
            for (int c = t; c < Lk; c += 256)
                wmean[((size_t)b * Lq + gi) * Lk + c] = wacc[rr * LKP + c] * 0.125f;
        }
    }
}

// ---------------- small kernels ----------------

__global__ void softmax_kernel(const float* __restrict__ src, float* __restrict__ dst, int L)
{
    size_t row = blockIdx.x;
    const float* p = src + row * (size_t)L;
    float* o = dst + row * (size_t)L;
    int t = threadIdx.x;
    float vals[8];
    int cnt = (L + 255) / 256;
    float mx = -1e30f;
    for (int i = 0; i < cnt; i++) {
        int idx = t + i * 256;
        vals[i] = (idx < L) ? p[idx] : -1e30f;
        mx = fmaxf(mx, vals[i]);
    }
    __shared__ float red[256];
    red[t] = mx; __syncthreads();
    for (int s = 128; s > 0; s >>= 1) { if (t < s) red[t] = fmaxf(red[t], red[t + s]); __syncthreads(); }
    mx = red[0]; __syncthreads();
    float sum = 0.f;
    for (int i = 0; i < cnt; i++) {
        int idx = t + i * 256;
        if (idx < L) { vals[i] = expf(vals[i] - mx); sum += vals[i]; }
    }
    red[t] = sum; __syncthreads();
    for (int s = 128; s > 0; s >>= 1) { if (t < s) red[t] += red[t + s]; __syncthreads(); }
    float inv = 1.f / red[0];
    for (int i = 0; i < cnt; i++) {
        int idx = t + i * 256;
        if (idx < L) o[idx] = vals[i] * inv;
    }
}

__global__ void add_ln_kernel(const float* __restrict__ a, const float* __restrict__ b,
                              const float* __restrict__ c,
                              const float* __restrict__ g, const float* __restrict__ bet,
                              float* __restrict__ out)
{
    size_t row = blockIdx.x;
    int t = threadIdx.x;
    float x = a[row * DD + t] + b[row * DD + t];
    if (c) x += c[row * DD + t];
    __shared__ float red[256];
    red[t] = x; __syncthreads();
    for (int s = 128; s > 0; s >>= 1) { if (t < s) red[t] += red[t + s]; __syncthreads(); }
    float mean = red[0] * (1.f / DD); __syncthreads();
    float d = x - mean;
    red[t] = d * d; __syncthreads();
    for (int s = 128; s > 0; s >>= 1) { if (t < s) red[t] += red[t + s]; __syncthreads(); }
    float var = red[0] * (1.f / DD);
    out[row * DD + t] = d * rsqrtf(var + 1e-5f) * g[t] + bet[t];
}

__global__ void embed_kernel(const int* __restrict__ q, const int* __restrict__ r,
                             const int* __restrict__ qry,
                             const float* __restrict__ M_emb, const float* __restrict__ E_emb,
                             const float* __restrict__ P,
                             float* __restrict__ M, float* __restrict__ E)
{
    int row = blockIdx.x; int t = threadIdx.x;
    int n = row % NN;
    int x = q[row] + NQ * r[row];
    M[(size_t)row * DD + t] = M_emb[(size_t)x * DD + t] + P[n * DD + t];
    E[(size_t)row * DD + t] = E_emb[(size_t)qry[row] * DD + t];
}

__global__ void gather_skill_kernel(const int* __restrict__ q, const float* __restrict__ rep,
                                    float* __restrict__ out)
{
    int row = blockIdx.x; int t = threadIdx.x;
    out[(size_t)row * DD + t] = rep[(size_t)q[row] * DD + t];
}

__global__ void gather_loc_kernel(const float* __restrict__ Sb, float* __restrict__ loc)
{
    int row = blockIdx.x; int t = threadIdx.x;
    int b = row / LWW, j = row % LWW;
    loc[(size_t)row * DD + t] = Sb[((size_t)(b * NN + NN - LWW + j)) * DD + t];
}

__global__ void scatter_loc_kernel(const float* __restrict__ locout, float* __restrict__ Sl)
{
    int row = blockIdx.x; int t = threadIdx.x;
    int b = row / LWW, j = row % LWW;
    Sl[((size_t)(b * NN + NN - LWW + j)) * DD + t] = locout[(size_t)row * DD + t];
}

__global__ void fill_zero_kernel(float* __restrict__ p, size_t n)
{
    size_t i = (size_t)blockIdx.x * 256 + threadIdx.x;
    if (i < n) p[i] = 0.f;
}

__global__ void sum6_kernel(const float* a, const float* b, const float* c,
                            const float* d, const float* e, const float* f,
                            float* __restrict__ out, size_t n)
{
    size_t i = (size_t)blockIdx.x * 256 + threadIdx.x;
    if (i < n) out[i] = a[i] + b[i] + c[i] + d[i] + e[i] + f[i];
}

__global__ void pred_kernel(const float* __restrict__ F, const float* __restrict__ w,
                            const float* __restrict__ b, float* __restrict__ out)
{
    size_t row = blockIdx.x;
    int t = threadIdx.x;
    float v = F[row * DD + t] * w[t];
    __shared__ float red[256];
    red[t] = v; __syncthreads();
    for (int s = 128; s > 0; s >>= 1) { if (t < s) red[t] += red[t + s]; __syncthreads(); }
    if (t == 0) out[row] = 1.f / (1.f + expf(-(red[0] + b[0])));
}

// ---------------- host orchestration ----------------

static void g128(const float* X, const float* W, const float* bias, float* Y,
                 int M, int K, int Nout, int act = 0,
                 int batch = 1, long sX = 0, long sW = 0, long sY = 0)
{
    dim3 grid((Nout + 127) / 128, (M + 127) / 128, batch);
    gemm128_kernel<<<grid, 256>>>(X, W, bias, Y, M, K, Nout, act, sX, sW, sY);
}

static void run_attn(const float* Q, int sQ, const float* K, const float* V, int sKV,
                     float* O, float* wmean, int Lq, int Lk, int causal)
{
    int NC = (Lk + 127) / 128;
    int LKP = NC * 128 + 1;
    size_t smem = (size_t)(32 * 36 + 128 * 36 + 32 + 32 * LKP * (wmean ? 2 : 1)) * 4;
    cudaFuncSetAttribute(attn_fused, cudaFuncAttributeMaxDynamicSharedMemorySize, 160 * 1024);
    dim3 grid((Lq + 31) / 32, BB);
    attn_fused<<<grid, 256, smem>>>(Q, sQ, K, V, sKV, O, wmean, Lq, Lk, NC, causal);
}

#define GETSYM(var, symbol) float* var; { void* _p = nullptr; cudaGetSymbolAddress(&_p, symbol); var = (float*)_p; }

extern "C" void kernel_launch(void* const* d_in, const int* in_sizes, int n_in,
                              void* d_out, int out_size)
{
    const int*   q    = (const int*)d_in[0];
    const int*   r    = (const int*)d_in[1];
    const int*   qry  = (const int*)d_in[2];
    const float* M_emb = (const float*)d_in[3];
    const float* E_emb = (const float*)d_in[4];
    const float* P     = (const float*)d_in[5];
    const float* attn_in_w  = (const float*)d_in[6];
    const float* attn_in_b  = (const float*)d_in[7];
    const float* attn_out_w = (const float*)d_in[8];
    const float* attn_out_b = (const float*)d_in[9];
    const float* skill_cw   = (const float*)d_in[10];
    const float* skill_pw   = (const float*)d_in[11];
    const float* skill_pb   = (const float*)d_in[12];
    const float* skill_ew   = (const float*)d_in[13];
    const float* skill_eb   = (const float*)d_in[14];
    const float* ffn_w1 = (const float*)d_in[15];
    const float* ffn_b1 = (const float*)d_in[16];
    const float* ffn_w2 = (const float*)d_in[17];
    const float* ffn_b2 = (const float*)d_in[18];
    const float* ln1_g  = (const float*)d_in[19];
    const float* ln1_b  = (const float*)d_in[20];
    const float* ln2_g  = (const float*)d_in[21];
    const float* ln2_b  = (const float*)d_in[22];
    const float* pred_w = (const float*)d_in[23];
    const float* pred_b = (const float*)d_in[24];

    float* out_p = (float*)d_out;                 // (B, N)
    float* out_attn = out_p + BB * NN;            // (B, N, N)

    GETSYM(pM, g_M);   GETSYM(pE, g_E);   GETSYM(pSbase, g_Sbase); GETSYM(pSlocal, g_Slocal);
    GETSYM(pSsg, g_Ssg); GETSYM(pSglob, g_Sglob); GETSYM(pSbl, g_Sbl); GETSYM(pSsgl, g_Ssgl);
    GETSYM(pQKV, g_QKV); GETSYM(pQb, g_Qb); GETSYM(pKV, g_KV); GETSYM(pOh, g_Oh); GETSYM(pT, g_T);
    GETSYM(pSW, g_SW); GETSYM(psrep, g_srep); GETSYM(psgr, g_sgr);
    GETSYM(psg1, g_sg1); GETSYM(psg2, g_sg2);
    GETSYM(ploc, g_loc); GETSYM(plocout, g_locout);
    GETSYM(psum, g_sum); GETSYM(pf1, g_f1); GETSYM(pF, g_F);

    const size_t BND = (size_t)BB * NN * DD;
    const int MR = BB * NN;     // 16384 rows
    const int W3 = 3 * DD * DD, B3 = 3 * DD, W1 = DD * DD;

    // 1. embeddings
    embed_kernel<<<BB * NN, 256>>>(q, r, qry, M_emb, E_emb, P, pM, pE);

    // 2. attn0: q=E, kv=M, causal, head-mean weights -> out_attn
    g128(pE, attn_in_w, attn_in_b, pQb, MR, DD, DD);                          // Q
    g128(pM, attn_in_w + DD * DD, attn_in_b + DD, pKV, MR, DD, 2 * DD);      // K,V
    run_attn(pQb, DD, pKV, pKV + DD, 2 * DD, pOh, out_attn, NN, NN, 1);
    g128(pOh, attn_out_w, attn_out_b, pT, MR, DD, DD);

    // 3. S_base = LN(attn0 + M + E)
    add_ln_kernel<<<BB * NN, 256>>>(pT, pM, pE, ln1_g, ln1_b, pSbase);

    // 4. local attention on last LW rows
    gather_loc_kernel<<<BB * LWW, 256>>>(pSbase, ploc);
    g128(ploc, attn_in_w + 1 * W3, attn_in_b + 1 * B3, pQKV, BB * LWW, DD, 3 * DD);
    run_attn(pQKV, 3 * DD, pQKV + DD, pQKV + 2 * DD, 3 * DD, pOh, nullptr, LWW, LWW, 1);
    g128(pOh, attn_out_w + 1 * W1, attn_out_b + 1 * DD, plocout, BB * LWW, DD, DD);
    fill_zero_kernel<<<(unsigned)((BND + 255) / 256), 256>>>(pSlocal, BND);
    scatter_loc_kernel<<<BB * LWW, 256>>>(plocout, pSlocal);

    // 5. skill path
    softmax_kernel<<<NQ, 256>>>(skill_cw, pSW, NQ);
    g128(pSW, skill_pw, skill_pb, psrep, NQ, NQ, DD);
    gather_skill_kernel<<<BB * NN, 256>>>(q, psrep, psgr);

    // 6. S_sg1[b] = S_base[b] @ sgr[b]^T  (batched, M=512,K=256,N=512)
    g128(pSbase, psgr, nullptr, psg1, NN, DD, NN, 0, BB,
         (long)NN * DD, (long)NN * DD, (long)NN * NN);

    // 7. S_sg2 = S_sg1 @ skill_to_embed_w^T + b
    g128(psg1, skill_ew, skill_eb, psg2, MR, NN, DD);

    // 8. attn2 (self, no mask) on S_sg2 -> pSsg
    g128(psg2, attn_in_w + 2 * W3, attn_in_b + 2 * B3, pQKV, MR, DD, 3 * DD);
    run_attn(pQKV, 3 * DD, pQKV + DD, pQKV + 2 * DD, 3 * DD, pOh, nullptr, NN, NN, 0);
    g128(pOh, attn_out_w + 2 * W1, attn_out_b + 2 * DD, pSsg, MR, DD, DD);

    // 9. attn3 (self, causal) on S_base -> pSglob
    g128(pSbase, attn_in_w + 3 * W3, attn_in_b + 3 * B3, pQKV, MR, DD, 3 * DD);
    run_attn(pQKV, 3 * DD, pQKV + DD, pQKV + 2 * DD, 3 * DD, pOh, nullptr, NN, NN, 1);
    g128(pOh, attn_out_w + 3 * W1, attn_out_b + 3 * DD, pSglob, MR, DD, DD);

    // 10. attn4: q=S_base, kv=S_local, no mask -> pSbl
    g128(pSbase, attn_in_w + 4 * W3, attn_in_b + 4 * B3, pQb, MR, DD, DD);
    g128(pSlocal, attn_in_w + 4 * W3 + DD * DD, attn_in_b + 4 * B3 + DD, pKV, MR, DD, 2 * DD);
    run_attn(pQb, DD, pKV, pKV + DD, 2 * DD, pOh, nullptr, NN, NN, 0);
    g128(pOh, attn_out_w + 4 * W1, attn_out_b + 4 * DD, pSbl, MR, DD, DD);

    // 11. attn5: q=S_sg, kv=S_glob, no mask -> pSsgl
    g128(pSsg, attn_in_w + 5 * W3, attn_in_b + 5 * B3, pQb, MR, DD, DD);
    g128(pSglob, attn_in_w + 5 * W3 + DD * DD, attn_in_b + 5 * B3 + DD, pKV, MR, DD, 2 * DD);
    run_attn(pQb, DD, pKV, pKV + DD, 2 * DD, pOh, nullptr, NN, NN, 0);
    g128(pOh, attn_out_w + 5 * W1, attn_out_b + 5 * DD, pSsgl, MR, DD, DD);

    // 12. S = sum of six streams
    sum6_kernel<<<(unsigned)((BND + 255) / 256), 256>>>(pSbase, pSlocal, pSsg, pSglob, pSbl, pSsgl,
                                                        psum, BND);

    // 13. FFN + residual + LN2
    g128(psum, ffn_w1, ffn_b1, pf1, MR, DD, DD, 1);
    g128(pf1, ffn_w2, ffn_b2, pT, MR, DD, DD);
    add_ln_kernel<<<BB * NN, 256>>>(pT, psum, nullptr, ln2_g, ln2_b, pF);

    // 14. prediction head
    pred_kernel<<<BB * NN, 256>>>(pF, pred_w, pred_b, out_p);
}

// round 3
// speedup vs baseline: 1.9668x; 1.4758x over previous
#include <cuda_runtime.h>
#include <math.h>

#define BB 32
#define NN 512
#define DD 256
#define HH 8
#define HD 32
#define LWW 25
#define NQ 2048

typedef unsigned long long ull;
#define FFMA2(d, a, b) asm("fma.rn.f32x2 %0, %1, %2, %3;" : "=l"(d) : "l"(a), "l"(b), "l"(d))
#define MUL2(d, a, b)  asm("mul.rn.f32x2 %0, %1, %2;" : "=l"(d) : "l"(a), "l"(b))
#define PACK2(d, s)    asm("mov.b64 %0, {%1, %1};" : "=l"(d) : "f"(s))

// ---------------- scratch ----------------
__device__ float g_M[BB*NN*DD];
__device__ float g_E[BB*NN*DD];
__device__ float g_Sbase[BB*NN*DD];
__device__ float g_Slocal[BB*NN*DD];
__device__ float g_Ssg[BB*NN*DD];
__device__ float g_Sglob[BB*NN*DD];
__device__ float g_Sbl[BB*NN*DD];
__device__ float g_Ssgl[BB*NN*DD];
__device__ float g_QKV[BB*NN*3*DD];
__device__ float g_Qb[BB*NN*DD];
__device__ float g_KV[BB*NN*2*DD];
__device__ float g_Oh[BB*NN*DD];
__device__ float g_T[BB*NN*DD];
__device__ float g_SW[NQ*NQ];
__device__ float g_srep[NQ*DD];
__device__ float g_sgr[BB*NN*DD];
__device__ float g_sg1[BB*NN*NN];
__device__ float g_sg2[BB*NN*DD];
__device__ float g_loc[BB*LWW*DD];
__device__ float g_locout[BB*LWW*DD];
__device__ float g_sum[BB*NN*DD];
__device__ float g_f1[BB*NN*DD];
__device__ float g_F[BB*NN*DD];
__device__ float g_sm[BB*HH*NN];
__device__ float g_sl[BB*HH*NN];

// ---------------- GEMM (unchanged from R2) ----------------
__global__ __launch_bounds__(256) void gemm128_kernel(
    const float* __restrict__ X, const float* __restrict__ W,
    const float* __restrict__ bias, float* __restrict__ Y,
    int M, int K, int Nout, int act,
    long sX, long sW, long sY)
{
    X += (size_t)blockIdx.z * sX;
    W += (size_t)blockIdx.z * sW;
    Y += (size_t)blockIdx.z * sY;

    __shared__ float As2[16][256];
    __shared__ float Bs[16][128];

    int t = threadIdx.x;
    int tx = t & 15, ty = t >> 4;
    int m0 = blockIdx.y * 128, n0 = blockIdx.x * 128;

    ull acc[8][4];
    #pragma unroll
    for (int i = 0; i < 8; i++)
        #pragma unroll
        for (int j = 0; j < 4; j++) acc[i][j] = 0ull;

    for (int k0 = 0; k0 < K; k0 += 16) {
        #pragma unroll
        for (int l = 0; l < 2; l++) {
            int id = t + l * 256;
            int r = id >> 2, c = (id & 3) * 4;
            int gm = m0 + r;
            float4 v = make_float4(0.f, 0.f, 0.f, 0.f);
            if (gm < M) v = *(const float4*)&X[(size_t)gm * K + k0 + c];
            *(float2*)&As2[c + 0][2 * r] = make_float2(v.x, v.x);
            *(float2*)&As2[c + 1][2 * r] = make_float2(v.y, v.y);
            *(float2*)&As2[c + 2][2 * r] = make_float2(v.z, v.z);
            *(float2*)&As2[c + 3][2 * r] = make_float2(v.w, v.w);
            int gn = n0 + r;
            float4 w = make_float4(0.f, 0.f, 0.f, 0.f);
            if (gn < Nout) w = *(const float4*)&W[(size_t)gn * K + k0 + c];
            Bs[c + 0][r] = w.x; Bs[c + 1][r] = w.y; Bs[c + 2][r] = w.z; Bs[c + 3][r] = w.w;
        }
        __syncthreads();
        #pragma unroll
        for (int k = 0; k < 16; k++) {
            ull a2[8];
            #pragma unroll
            for (int i = 0; i < 8; i++)
                a2[i] = *(const ull*)&As2[k][2 * (ty * 8 + i)];
            ull b2[4];
            float4 bA = *(const float4*)&Bs[k][tx * 8];
            float4 bB = *(const float4*)&Bs[k][tx * 8 + 4];
            b2[0] = ((const ull*)&bA)[0]; b2[1] = ((const ull*)&bA)[1];
            b2[2] = ((const ull*)&bB)[0]; b2[3] = ((const ull*)&bB)[1];
            #pragma unroll
            for (int i = 0; i < 8; i++)
                #pragma unroll
                for (int j = 0; j < 4; j++)
                    FFMA2(acc[i][j], a2[i], b2[j]);
        }
        __syncthreads();
    }

    #pragma unroll
    for (int i = 0; i < 8; i++) {
        int gm = m0 + ty * 8 + i;
        if (gm >= M) continue;
        float res[8];
        #pragma unroll
        for (int j = 0; j < 4; j++) {
            float2 p = *(float2*)&acc[i][j];
            res[2 * j] = p.x; res[2 * j + 1] = p.y;
        }
        #pragma unroll
        for (int j = 0; j < 8; j++) {
            int gn = n0 + tx * 8 + j;
            if (gn >= Nout) continue;
            float v = res[j] + (bias ? bias[gn] : 0.f);
            if (act == 1) v = fmaxf(v, 0.f);
            Y[(size_t)gm * Nout + gn] = v;
        }
    }
}

// ---------------- flash attention ----------------
// grid ((Lq+63)/64, B*H), block 256. smem = 52224 B.
// Qt2[32][132] dup | Kt[32][68] | Ps[64][68] | Vs[64][36]
__global__ __launch_bounds__(256) void attn_flash(
    const float* __restrict__ Qm, int sQ,
    const float* __restrict__ Km, const float* __restrict__ Vm, int sKV,
    float* __restrict__ O, float* __restrict__ stats_m, float* __restrict__ stats_l,
    int Lq, int Lk, int causal)
{
    extern __shared__ float sm[];
    float* Qt2 = sm;            // 4224
    float* Kt  = sm + 4224;     // 2176
    float* Ps  = sm + 6400;     // 4352
    float* Vs  = sm + 10752;    // 2304

    int bh = blockIdx.y;
    int b = bh >> 3, h = bh & 7;
    int i0 = blockIdx.x * 64;
    int t = threadIdx.x;
    int ty = t >> 4, tx = t & 15;
    int ri = ty * 4;
    const float scale = 0.1767766953f;

    // load Q (dup-transposed)
    {
        int r = t >> 2, k8 = (t & 3) * 8;
        int gi = i0 + r;
        float4 v0 = make_float4(0,0,0,0), v1 = make_float4(0,0,0,0);
        if (gi < Lq) {
            const float* qp = &Qm[(size_t)(b * Lq + gi) * sQ + h * HD + k8];
            v0 = *(const float4*)qp; v1 = *(const float4*)(qp + 4);
        }
        float vv[8] = {v0.x, v0.y, v0.z, v0.w, v1.x, v1.y, v1.z, v1.w};
        #pragma unroll
        for (int kk = 0; kk < 8; kk++)
            *(float2*)&Qt2[(k8 + kk) * 132 + 2 * r] = make_float2(vv[kk], vv[kk]);
    }

    float m[4], l[4];
    ull o2[4];
    #pragma unroll
    for (int u = 0; u < 4; u++) { m[u] = -1e30f; l[u] = 0.f; o2[u] = 0ull; }

    int nkc = (Lk + 63) >> 6;
    if (causal) { int mx = (i0 >> 6) + 1; if (mx < nkc) nkc = mx; }

    for (int kc = 0; kc < nkc; kc++) {
        __syncthreads();
        // load K (transposed) + V (row-major)
        {
            int j = t >> 2, k8 = (t & 3) * 8;
            int gj = kc * 64 + j;
            float4 v0 = make_float4(0,0,0,0), v1 = make_float4(0,0,0,0);
            float4 w0 = make_float4(0,0,0,0), w1 = make_float4(0,0,0,0);
            if (gj < Lk) {
                const float* kp = &Km[(size_t)(b * Lk + gj) * sKV + h * HD + k8];
                v0 = *(const float4*)kp; v1 = *(const float4*)(kp + 4);
                const float* vp = &Vm[(size_t)(b * Lk + gj) * sKV + h * HD + k8];
                w0 = *(const float4*)vp; w1 = *(const float4*)(vp + 4);
            }
            float vv[8] = {v0.x, v0.y, v0.z, v0.w, v1.x, v1.y, v1.z, v1.w};
            #pragma unroll
            for (int kk = 0; kk < 8; kk++) Kt[(k8 + kk) * 68 + j] = vv[kk];
            *(float4*)&Vs[j * 36 + k8] = w0;
            *(float4*)&Vs[j * 36 + k8 + 4] = w1;
        }
        __syncthreads();

        // scores 4x4 (f32x2)
        ull acc2[4][2];
        #pragma unroll
        for (int u = 0; u < 4; u++) { acc2[u][0] = 0ull; acc2[u][1] = 0ull; }
        #pragma unroll
        for (int k = 0; k < 32; k++) {
            const float* qrow = &Qt2[k * 132 + 2 * ri];
            ull a0 = *(const ull*)&qrow[0];
            ull a1 = *(const ull*)&qrow[2];
            ull aa2 = *(const ull*)&qrow[4];
            ull a3 = *(const ull*)&qrow[6];
            float4 bv = *(const float4*)&Kt[k * 68 + tx * 4];
            ull b0 = ((const ull*)&bv)[0], b1 = ((const ull*)&bv)[1];
            FFMA2(acc2[0][0], a0, b0);  FFMA2(acc2[0][1], a0, b1);
            FFMA2(acc2[1][0], a1, b0);  FFMA2(acc2[1][1], a1, b1);
            FFMA2(acc2[2][0], aa2, b0); FFMA2(acc2[2][1], aa2, b1);
            FFMA2(acc2[3][0], a3, b0);  FFMA2(acc2[3][1], a3, b1);
        }

        // online softmax
        int c0 = kc * 64 + tx * 4;
        #pragma unroll
        for (int u = 0; u < 4; u++) {
            float2 pa = *(float2*)&acc2[u][0], pb = *(float2*)&acc2[u][1];
            float s0 = pa.x * scale, s1 = pa.y * scale, s2 = pb.x * scale, s3 = pb.y * scale;
            int gi = i0 + ri + u;
            if (c0 + 0 >= Lk || (causal && c0 + 0 > gi)) s0 = -1e30f;
            if (c0 + 1 >= Lk || (causal && c0 + 1 > gi)) s1 = -1e30f;
            if (c0 + 2 >= Lk || (causal && c0 + 2 > gi)) s2 = -1e30f;
            if (c0 + 3 >= Lk || (causal && c0 + 3 > gi)) s3 = -1e30f;
            float cm = fmaxf(fmaxf(s0, s1), fmaxf(s2, s3));
            #pragma unroll
            for (int off = 8; off; off >>= 1)
                cm = fmaxf(cm, __shfl_xor_sync(0xffffffffu, cm, off));
            float mn = fmaxf(m[u], cm);
            float alpha = __expf(m[u] - mn);
            float p0 = __expf(s0 - mn), p1 = __expf(s1 - mn);
            float p2v = __expf(s2 - mn), p3 = __expf(s3 - mn);
            float rs = (p0 + p1) + (p2v + p3);
            #pragma unroll
            for (int off = 8; off; off >>= 1)
                rs += __shfl_xor_sync(0xffffffffu, rs, off);
            l[u] = l[u] * alpha + rs;
            m[u] = mn;
            ull al2; PACK2(al2, alpha);
            MUL2(o2[u], o2[u], al2);
            *(float4*)&Ps[(ri + u) * 68 + tx * 4] = make_float4(p0, p1, p2v, p3);
        }
        __syncthreads();

        // PV (f32x2, dup P in regs)
        #pragma unroll 4
        for (int j4 = 0; j4 < 16; j4++) {
            int j = j4 * 4;
            float4 pr[4];
            #pragma unroll
            for (int u = 0; u < 4; u++)
                pr[u] = *(const float4*)&Ps[(ri + u) * 68 + j];
            #pragma unroll
            for (int jj = 0; jj < 4; jj++) {
                ull vj = *(const ull*)&Vs[(j + jj) * 36 + 2 * tx];
                #pragma unroll
                for (int u = 0; u < 4; u++) {
                    float pv = ((const float*)&pr[u])[jj];
                    ull d; PACK2(d, pv);
                    FFMA2(o2[u], d, vj);
                }
            }
        }
    }

    // epilogue
    #pragma unroll
    for (int u = 0; u < 4; u++) {
        int gi = i0 + ri + u;
        if (gi >= Lq) continue;
        float inv = 1.f / l[u];
        float2 ov = *(float2*)&o2[u];
        ov.x *= inv; ov.y *= inv;
        *(float2*)&O[(size_t)(b * Lq + gi) * DD + h * HD + 2 * tx] = ov;
        if (stats_m && tx == 0) {
            stats_m[(size_t)bh * Lq + gi] = m[u];
            stats_l[(size_t)bh * Lq + gi] = l[u];
        }
    }
}

// ---------------- wmean pass2: out[b,i,j] = mean_h exp(s-m)/l * (1/8) ----------------
// grid (8 qtiles, 32 b, 8 kc), block 256
__global__ __launch_bounds__(256) void wmean_kernel(
    const float* __restrict__ Qm, int sQ,
    const float* __restrict__ Km, int sKV,
    const float* __restrict__ stats_m, const float* __restrict__ stats_l,
    float* __restrict__ out)
{
    __shared__ float Qt2[32 * 132];
    __shared__ float Kt[32 * 68];

    int qt = blockIdx.x, b = blockIdx.y, kc = blockIdx.z;
    int i0 = qt * 64;
    int t = threadIdx.x;
    int ty = t >> 4, tx = t & 15;
    int ri = ty * 4;
    const float scale = 0.1767766953f;

    float macc[4][4];
    #pragma unroll
    for (int u = 0; u < 4; u++)
        #pragma unroll
        for (int v = 0; v < 4; v++) macc[u][v] = 0.f;

    for (int h = 0; h < HH; h++) {
        __syncthreads();
        {
            int r = t >> 2, k8 = (t & 3) * 8;
            int gi = i0 + r;
            const float* qp = &Qm[(size_t)(b * NN + gi) * sQ + h * HD + k8];
            float4 v0 = *(const float4*)qp, v1 = *(const float4*)(qp + 4);
            float vv[8] = {v0.x, v0.y, v0.z, v0.w, v1.x, v1.y, v1.z, v1.w};
            #pragma unroll
            for (int kk = 0; kk < 8; kk++)
                *(float2*)&Qt2[(k8 + kk) * 132 + 2 * r] = make_float2(vv[kk], vv[kk]);
            int gj = kc * 64 + r;
            const float* kp = &Km[(size_t)(b * NN + gj) * sKV + h * HD + k8];
            float4 w0 = *(const float4*)kp, w1 = *(const float4*)(kp + 4);
            float ww[8] = {w0.x, w0.y, w0.z, w0.w, w1.x, w1.y, w1.z, w1.w};
            #pragma unroll
            for (int kk = 0; kk < 8; kk++) Kt[(k8 + kk) * 68 + r] = ww[kk];
        }
        __syncthreads();

        ull acc2[4][2];
        #pragma unroll
        for (int u = 0; u < 4; u++) { acc2[u][0] = 0ull; acc2[u][1] = 0ull; }
        #pragma unroll
        for (int k = 0; k < 32; k++) {
            const float* qrow = &Qt2[k * 132 + 2 * ri];
            ull a0 = *(const ull*)&qrow[0];
            ull a1 = *(const ull*)&qrow[2];
            ull aa2 = *(const ull*)&qrow[4];
            ull a3 = *(const ull*)&qrow[6];
            float4 bv = *(const float4*)&Kt[k * 68 + tx * 4];
            ull b0 = ((const ull*)&bv)[0], b1 = ((const ull*)&bv)[1];
            FFMA2(acc2[0][0], a0, b0);  FFMA2(acc2[0][1], a0, b1);
            FFMA2(acc2[1][0], a1, b0);  FFMA2(acc2[1][1], a1, b1);
            FFMA2(acc2[2][0], aa2, b0); FFMA2(acc2[2][1], aa2, b1);
            FFMA2(acc2[3][0], a3, b0);  FFMA2(acc2[3][1], a3, b1);
        }

        int c0 = kc * 64 + tx * 4;
        #pragma unroll
        for (int u = 0; u < 4; u++) {
            int gi = i0 + ri + u;
            float mrow = stats_m[((size_t)(b * HH + h)) * NN + gi];
            float linv = 1.f / stats_l[((size_t)(b * HH + h)) * NN + gi];
            float2 pa = *(float2*)&acc2[u][0], pb = *(float2*)&acc2[u][1];
            float s[4] = {pa.x, pa.y, pb.x, pb.y};
            #pragma unroll
            for (int v = 0; v < 4; v++) {
                if (c0 + v <= gi)
                    macc[u][v] += __expf(s[v] * scale - mrow) * linv;
            }
        }
    }

    #pragma unroll
    for (int u = 0; u < 4; u++) {
        int gi = i0 + ri + u;
        float4 ov = make_float4(macc[u][0] * 0.125f, macc[u][1] * 0.125f,
                                macc[u][2] * 0.125f, macc[u][3] * 0.125f);
        *(float4*)&out[((size_t)(b * NN) + gi) * NN + kc * 64 + tx * 4] = ov;
    }
}

// ---------------- small kernels ----------------

__global__ void softmax_kernel(const float* __restrict__ src, float* __restrict__ dst, int L)
{
    size_t row = blockIdx.x;
    const float* p = src + row * (size_t)L;
    float* o = dst + row * (size_t)L;
    int t = threadIdx.x;
    float vals[8];
    int cnt = (L + 255) / 256;
    float mx = -1e30f;
    for (int i = 0; i < cnt; i++) {
        int idx = t + i * 256;
        vals[i] = (idx < L) ? p[idx] : -1e30f;
        mx = fmaxf(mx, vals[i]);
    }
    __shared__ float red[256];
    red[t] = mx; __syncthreads();
    for (int s = 128; s > 0; s >>= 1) { if (t < s) red[t] = fmaxf(red[t], red[t + s]); __syncthreads(); }
    mx = red[0]; __syncthreads();
    float sum = 0.f;
    for (int i = 0; i < cnt; i++) {
        int idx = t + i * 256;
        if (idx < L) { vals[i] = expf(vals[i] - mx); sum += vals[i]; }
    }
    red[t] = sum; __syncthreads();
    for (int s = 128; s > 0; s >>= 1) { if (t < s) red[t] += red[t + s]; __syncthreads(); }
    float inv = 1.f / red[0];
    for (int i = 0; i < cnt; i++) {
        int idx = t + i * 256;
        if (idx < L) o[idx] = vals[i] * inv;
    }
}

__global__ void add_ln_kernel(const float* __restrict__ a, const float* __restrict__ b,
                              const float* __restrict__ c,
                              const float* __restrict__ g, const float* __restrict__ bet,
                              float* __restrict__ out)
{
    size_t row = blockIdx.x;
    int t = threadIdx.x;
    float x = a[row * DD + t] + b[row * DD + t];
    if (c) x += c[row * DD + t];
    __shared__ float red[256];
    red[t] = x; __syncthreads();
    for (int s = 128; s > 0; s >>= 1) { if (t < s) red[t] += red[t + s]; __syncthreads(); }
    float mean = red[0] * (1.f / DD); __syncthreads();
    float d = x - mean;
    red[t] = d * d; __syncthreads();
    for (int s = 128; s > 0; s >>= 1) { if (t < s) red[t] += red[t + s]; __syncthreads(); }
    float var = red[0] * (1.f / DD);
    out[row * DD + t] = d * rsqrtf(var + 1e-5f) * g[t] + bet[t];
}

__global__ void embed_kernel(const int* __restrict__ q, const int* __restrict__ r,
                             const int* __restrict__ qry,
                             const float* __restrict__ M_emb, const float* __restrict__ E_emb,
                             const float* __restrict__ P,
                             float* __restrict__ M, float* __restrict__ E)
{
    int row = blockIdx.x; int t = threadIdx.x;
    int n = row % NN;
    int x = q[row] + NQ * r[row];
    M[(size_t)row * DD + t] = M_emb[(size_t)x * DD + t] + P[n * DD + t];
    E[(size_t)row * DD + t] = E_emb[(size_t)qry[row] * DD + t];
}

__global__ void gather_skill_kernel(const int* __restrict__ q, const float* __restrict__ rep,
                                    float* __restrict__ out)
{
    int row = blockIdx.x; int t = threadIdx.x;
    out[(size_t)row * DD + t] = rep[(size_t)q[row] * DD + t];
}

__global__ void gather_loc_kernel(const float* __restrict__ Sb, float* __restrict__ loc)
{
    int row = blockIdx.x; int t = threadIdx.x;
    int b = row / LWW, j = row % LWW;
    loc[(size_t)row * DD + t] = Sb[((size_t)(b * NN + NN - LWW + j)) * DD + t];
}

__global__ void scatter_loc_kernel(const float* __restrict__ locout, float* __restrict__ Sl)
{
    int row = blockIdx.x; int t = threadIdx.x;
    int b = row / LWW, j = row % LWW;
    Sl[((size_t)(b * NN + NN - LWW + j)) * DD + t] = locout[(size_t)row * DD + t];
}

__global__ void fill_zero_kernel(float* __restrict__ p, size_t n)
{
    size_t i = (size_t)blockIdx.x * 256 + threadIdx.x;
    if (i < n) p[i] = 0.f;
}

__global__ void sum6_kernel(const float* a, const float* b, const float* c,
                            const float* d, const float* e, const float* f,
                            float* __restrict__ out, size_t n)
{
    size_t i = (size_t)blockIdx.x * 256 + threadIdx.x;
    if (i < n) out[i] = a[i] + b[i] + c[i] + d[i] + e[i] + f[i];
}

__global__ void pred_kernel(const float* __restrict__ F, const float* __restrict__ w,
                            const float* __restrict__ b, float* __restrict__ out)
{
    size_t row = blockIdx.x;
    int t = threadIdx.x;
    float v = F[row * DD + t] * w[t];
    __shared__ float red[256];
    red[t] = v; __syncthreads();
    for (int s = 128; s > 0; s >>= 1) { if (t < s) red[t] += red[t + s]; __syncthreads(); }
    if (t == 0) out[row] = 1.f / (1.f + expf(-(red[0] + b[0])));
}

// ---------------- host orchestration ----------------

static void g128(const float* X, const float* W, const float* bias, float* Y,
                 int M, int K, int Nout, int act = 0,
                 int batch = 1, long sX = 0, long sW = 0, long sY = 0)
{
    dim3 grid((Nout + 127) / 128, (M + 127) / 128, batch);
    gemm128_kernel<<<grid, 256>>>(X, W, bias, Y, M, K, Nout, act, sX, sW, sY);
}

static void run_attn(const float* Q, int sQ, const float* K, const float* V, int sKV,
                     float* O, float* sm_, float* sl_, int Lq, int Lk, int causal)
{
    static bool attr_set = false;
    if (!attr_set) {
        cudaFuncSetAttribute(attn_flash, cudaFuncAttributeMaxDynamicSharedMemorySize, 64 * 1024);
        attr_set = true;
    }
    dim3 grid((Lq + 63) / 64, BB * HH);
    attn_flash<<<grid, 256, 52224>>>(Q, sQ, K, V, sKV, O, sm_, sl_, Lq, Lk, causal);
}

#define GETSYM(var, symbol) float* var; { void* _p = nullptr; cudaGetSymbolAddress(&_p, symbol); var = (float*)_p; }

extern "C" void kernel_launch(void* const* d_in, const int* in_sizes, int n_in,
                              void* d_out, int out_size)
{
    const int*   q    = (const int*)d_in[0];
    const int*   r    = (const int*)d_in[1];
    const int*   qry  = (const int*)d_in[2];
    const float* M_emb = (const float*)d_in[3];
    const float* E_emb = (const float*)d_in[4];
    const float* P     = (const float*)d_in[5];
    const float* attn_in_w  = (const float*)d_in[6];
    const float* attn_in_b  = (const float*)d_in[7];
    const float* attn_out_w = (const float*)d_in[8];
    const float* attn_out_b = (const float*)d_in[9];
    const float* skill_cw   = (const float*)d_in[10];
    const float* skill_pw   = (const float*)d_in[11];
    const float* skill_pb   = (const float*)d_in[12];
    const float* skill_ew   = (const float*)d_in[13];
    const float* skill_eb   = (const float*)d_in[14];
    const float* ffn_w1 = (const float*)d_in[15];
    const float* ffn_b1 = (const float*)d_in[16];
    const float* ffn_w2 = (const float*)d_in[17];
    const float* ffn_b2 = (const float*)d_in[18];
    const float* ln1_g  = (const float*)d_in[19];
    const float* ln1_b  = (const float*)d_in[20];
    const float* ln2_g  = (const float*)d_in[21];
    const float* ln2_b  = (const float*)d_in[22];
    const float* pred_w = (const float*)d_in[23];
    const float* pred_b = (const float*)d_in[24];

    float* out_p = (float*)d_out;
    float* out_attn = out_p + BB * NN;

    GETSYM(pM, g_M);   GETSYM(pE, g_E);   GETSYM(pSbase, g_Sbase); GETSYM(pSlocal, g_Slocal);
    GETSYM(pSsg, g_Ssg); GETSYM(pSglob, g_Sglob); GETSYM(pSbl, g_Sbl); GETSYM(pSsgl, g_Ssgl);
    GETSYM(pQKV, g_QKV); GETSYM(pQb, g_Qb); GETSYM(pKV, g_KV); GETSYM(pOh, g_Oh); GETSYM(pT, g_T);
    GETSYM(pSW, g_SW); GETSYM(psrep, g_srep); GETSYM(psgr, g_sgr);
    GETSYM(psg1, g_sg1); GETSYM(psg2, g_sg2);
    GETSYM(ploc, g_loc); GETSYM(plocout, g_locout);
    GETSYM(psum, g_sum); GETSYM(pf1, g_f1); GETSYM(pF, g_F);
    GETSYM(psm, g_sm); GETSYM(psl, g_sl);

    const size_t BND = (size_t)BB * NN * DD;
    const int MR = BB * NN;
    const int W3 = 3 * DD * DD, B3 = 3 * DD, W1 = DD * DD;

    // 1. embeddings
    embed_kernel<<<BB * NN, 256>>>(q, r, qry, M_emb, E_emb, P, pM, pE);

    // 2. attn0: q=E, kv=M, causal; flash saves per-row stats
    g128(pE, attn_in_w, attn_in_b, pQb, MR, DD, DD);
    g128(pM, attn_in_w + DD * DD, attn_in_b + DD, pKV, MR, DD, 2 * DD);
    run_attn(pQb, DD, pKV, pKV + DD, 2 * DD, pOh, psm, psl, NN, NN, 1);
    wmean_kernel<<<dim3(8, 32, 8), 256>>>(pQb, DD, pKV, 2 * DD, psm, psl, out_attn);
    g128(pOh, attn_out_w, attn_out_b, pT, MR, DD, DD);

    // 3. S_base = LN(attn0 + M + E)
    add_ln_kernel<<<BB * NN, 256>>>(pT, pM, pE, ln1_g, ln1_b, pSbase);

    // 4. local attention on last LW rows
    gather_loc_kernel<<<BB * LWW, 256>>>(pSbase, ploc);
    g128(ploc, attn_in_w + 1 * W3, attn_in_b + 1 * B3, pQKV, BB * LWW, DD, 3 * DD);
    run_attn(pQKV, 3 * DD, pQKV + DD, pQKV + 2 * DD, 3 * DD, pOh, nullptr, nullptr, LWW, LWW, 1);
    g128(pOh, attn_out_w + 1 * W1, attn_out_b + 1 * DD, plocout, BB * LWW, DD, DD);
    fill_zero_kernel<<<(unsigned)((BND + 255) / 256), 256>>>(pSlocal, BND);
    scatter_loc_kernel<<<BB * LWW, 256>>>(plocout, pSlocal);

    // 5. skill path
    softmax_kernel<<<NQ, 256>>>(skill_cw, pSW, NQ);
    g128(pSW, skill_pw, skill_pb, psrep, NQ, NQ, DD);
    gather_skill_kernel<<<BB * NN, 256>>>(q, psrep, psgr);

    // 6. S_sg1[b] = S_base[b] @ sgr[b]^T
    g128(pSbase, psgr, nullptr, psg1, NN, DD, NN, 0, BB,
         (long)NN * DD, (long)NN * DD, (long)NN * NN);

    // 7. S_sg2 = S_sg1 @ skill_to_embed_w^T + b
    g128(psg1, skill_ew, skill_eb, psg2, MR, NN, DD);

    // 8. attn2 (self, no mask) on S_sg2
    g128(psg2, attn_in_w + 2 * W3, attn_in_b + 2 * B3, pQKV, MR, DD, 3 * DD);
    run_attn(pQKV, 3 * DD, pQKV + DD, pQKV + 2 * DD, 3 * DD, pOh, nullptr, nullptr, NN, NN, 0);
    g128(pOh, attn_out_w + 2 * W1, attn_out_b + 2 * DD, pSsg, MR, DD, DD);

    // 9. attn3 (self, causal) on S_base
    g128(pSbase, attn_in_w + 3 * W3, attn_in_b + 3 * B3, pQKV, MR, DD, 3 * DD);
    run_attn(pQKV, 3 * DD, pQKV + DD, pQKV + 2 * DD, 3 * DD, pOh, nullptr, nullptr, NN, NN, 1);
    g128(pOh, attn_out_w + 3 * W1, attn_out_b + 3 * DD, pSglob, MR, DD, DD);

    // 10. attn4: q=S_base, kv=S_local, no mask
    g128(pSbase, attn_in_w + 4 * W3, attn_in_b + 4 * B3, pQb, MR, DD, DD);
    g128(pSlocal, attn_in_w + 4 * W3 + DD * DD, attn_in_b + 4 * B3 + DD, pKV, MR, DD, 2 * DD);
    run_attn(pQb, DD, pKV, pKV + DD, 2 * DD, pOh, nullptr, nullptr, NN, NN, 0);
    g128(pOh, attn_out_w + 4 * W1, attn_out_b + 4 * DD, pSbl, MR, DD, DD);

    // 11. attn5: q=S_sg, kv=S_glob, no mask
    g128(pSsg, attn_in_w + 5 * W3, attn_in_b + 5 * B3, pQb, MR, DD, DD);
    g128(pSglob, attn_in_w + 5 * W3 + DD * DD, attn_in_b + 5 * B3 + DD, pKV, MR, DD, 2 * DD);
    run_attn(pQb, DD, pKV, pKV + DD, 2 * DD, pOh, nullptr, nullptr, NN, NN, 0);
    g128(pOh, attn_out_w + 5 * W1, attn_out_b + 5 * DD, pSsgl, MR, DD, DD);

    // 12. S = sum of six streams
    sum6_kernel<<<(unsigned)((BND + 255) / 256), 256>>>(pSbase, pSlocal, pSsg, pSglob, pSbl, pSsgl,
                                                        psum, BND);

    // 13. FFN + residual + LN2
    g128(psum, ffn_w1, ffn_b1, pf1, MR, DD, DD, 1);
    g128(pf1, ffn_w2, ffn_b2, pT, MR, DD, DD);
    add_ln_kernel<<<BB * NN, 256>>>(pT, psum, nullptr, ln2_g, ln2_b, pF);

    // 14. prediction head
    pred_kernel<<<BB * NN, 256>>>(pF, pred_w, pred_b, out_p);
}

// round 5
// speedup vs baseline: 3.1537x; 1.6034x over previous
#include <cuda_runtime.h>
#include <math.h>
#include <stdint.h>

#define BB 32
#define NN 512
#define DD 256
#define HH 8
#define HD 32
#define LWW 25
#define NQ 2048

typedef unsigned long long ull;
#define FFMA2(d, a, b) asm("fma.rn.f32x2 %0, %1, %2, %3;" : "=l"(d) : "l"(a), "l"(b), "l"(d))
#define MUL2(d, a, b)  asm("mul.rn.f32x2 %0, %1, %2;" : "=l"(d) : "l"(a), "l"(b))
#define PACK2(d, s)    asm("mov.b64 %0, {%1, %1};" : "=l"(d) : "f"(s))

#define CVT_TF32(u, f) asm("cvt.rna.tf32.f32 %0, %1;" : "=r"(u) : "f"(f))
#define MMA_TF32(c, a0, a1, a2, a3, b0, b1) \
    asm volatile("mma.sync.aligned.m16n8k8.row.col.f32.tf32.tf32.f32 " \
        "{%0,%1,%2,%3}, {%4,%5,%6,%7}, {%8,%9}, {%0,%1,%2,%3};" \
        : "+f"((c)[0]), "+f"((c)[1]), "+f"((c)[2]), "+f"((c)[3]) \
        : "r"(a0), "r"(a1), "r"(a2), "r"(a3), "r"(b0), "r"(b1))

// ---------------- scratch ----------------
__device__ float g_M[BB*NN*DD];
__device__ float g_E[BB*NN*DD];
__device__ float g_Sbase[BB*NN*DD];
__device__ float g_Slocal[BB*NN*DD];
__device__ float g_Ssg[BB*NN*DD];
__device__ float g_Sglob[BB*NN*DD];
__device__ float g_Sbl[BB*NN*DD];
__device__ float g_Ssgl[BB*NN*DD];
__device__ float g_QKV[BB*NN*3*DD];
__device__ float g_Qb[BB*NN*DD];
__device__ float g_KV[BB*NN*2*DD];
__device__ float g_Oh[BB*NN*DD];
__device__ float g_T[BB*NN*DD];
__device__ float g_SW[NQ*NQ];
__device__ float g_srep[NQ*DD];
__device__ float g_sgr[BB*NN*DD];
__device__ float g_sg1[BB*NN*NN];
__device__ float g_sg2[BB*NN*DD];
__device__ float g_loc[BB*LWW*DD];
__device__ float g_locout[BB*LWW*DD];
__device__ float g_sum[BB*NN*DD];
__device__ float g_f1[BB*NN*DD];
__device__ float g_F[BB*NN*DD];
__device__ float g_sm[BB*HH*NN];
__device__ float g_sl[BB*HH*NN];

// ================= HMMA tf32 GEMM: Y[M,N] = X[M,K] @ W[N,K]^T + bias =================
// grid (Nout/128, ceil(M/128), batch), block 256 (8 warps = 2m x 4n), warp tile 64x32.
__global__ __launch_bounds__(256) void mma_gemm(
    const float* __restrict__ X, const float* __restrict__ W,
    const float* __restrict__ bias, float* __restrict__ Y,
    int M, int K, int Nout, int act,
    long long sX, long long sW, long long sY)
{
    __shared__ float As[128 * 36];
    __shared__ float Bs[128 * 36];

    X += (size_t)blockIdx.z * sX;
    W += (size_t)blockIdx.z * sW;
    Y += (size_t)blockIdx.z * sY;

    int t = threadIdx.x, lane = t & 31, warp = t >> 5;
    int wm = warp & 1, wn = warp >> 1;
    int m0 = blockIdx.y * 128, n0 = blockIdx.x * 128;
    int mbase = wm * 64, nbase = wn * 32;
    int lq = lane >> 2, lr = lane & 3;

    float acc[4][4][4];
    #pragma unroll
    for (int mi = 0; mi < 4; mi++)
        #pragma unroll
        for (int nj = 0; nj < 4; nj++)
            #pragma unroll
            for (int c = 0; c < 4; c++) acc[mi][nj][c] = 0.f;

    for (int k0 = 0; k0 < K; k0 += 32) {
        __syncthreads();
        // copy chunk (tf32-converted, lane-rotated stores: conflict-free)
        #pragma unroll
        for (int l = 0; l < 4; l++) {
            int s = t + l * 256;
            int r = s >> 3, c4 = s & 7;
            int gm = m0 + r;
            float4 v = make_float4(0.f, 0.f, 0.f, 0.f);
            if (gm < M) v = *(const float4*)&X[(size_t)gm * K + k0 + c4 * 4];
            uint32_t ua[4];
            CVT_TF32(ua[0], v.x); CVT_TF32(ua[1], v.y);
            CVT_TF32(ua[2], v.z); CVT_TF32(ua[3], v.w);
            int gn = n0 + r;
            float4 w = make_float4(0.f, 0.f, 0.f, 0.f);
            if (gn < Nout) w = *(const float4*)&W[(size_t)gn * K + k0 + c4 * 4];
            uint32_t ub[4];
            CVT_TF32(ub[0], w.x); CVT_TF32(ub[1], w.y);
            CVT_TF32(ub[2], w.z); CVT_TF32(ub[3], w.w);
            #pragma unroll
            for (int j = 0; j < 4; j++) {
                int jj = (j + lane) & 3;
                As[r * 36 + c4 * 4 + jj] = __uint_as_float(ua[jj]);
                Bs[r * 36 + c4 * 4 + jj] = __uint_as_float(ub[jj]);
            }
        }
        __syncthreads();

        #pragma unroll
        for (int ks = 0; ks < 4; ks++) {
            int kk = ks * 8;
            uint32_t a[4][4], b[4][2];
            #pragma unroll
            for (int mi = 0; mi < 4; mi++) {
                int row = mbase + mi * 16 + lq;
                a[mi][0] = __float_as_uint(As[row * 36 + kk + lr]);
                a[mi][1] = __float_as_uint(As[(row + 8) * 36 + kk + lr]);
                a[mi][2] = __float_as_uint(As[row * 36 + kk + lr + 4]);
                a[mi][3] = __float_as_uint(As[(row + 8) * 36 + kk + lr + 4]);
            }
            #pragma unroll
            for (int nj = 0; nj < 4; nj++) {
                int nr = nbase + nj * 8 + lq;
                b[nj][0] = __float_as_uint(Bs[nr * 36 + kk + lr]);
                b[nj][1] = __float_as_uint(Bs[nr * 36 + kk + lr + 4]);
            }
            #pragma unroll
            for (int mi = 0; mi < 4; mi++)
                #pragma unroll
                for (int nj = 0; nj < 4; nj++)
                    MMA_TF32(acc[mi][nj], a[mi][0], a[mi][1], a[mi][2], a[mi][3],
                             b[nj][0], b[nj][1]);
        }
    }

    // epilogue: bias/relu fused, float2 stores
    #pragma unroll
    for (int nj = 0; nj < 4; nj++) {
        int col = n0 + nbase + nj * 8 + 2 * lr;
        float bx = 0.f, by = 0.f;
        if (bias) { bx = bias[col]; by = bias[col + 1]; }
        #pragma unroll
        for (int mi = 0; mi < 4; mi++) {
            int row = m0 + mbase + mi * 16 + lq;
            float v0 = acc[mi][nj][0] + bx, v1 = acc[mi][nj][1] + by;
            float v2 = acc[mi][nj][2] + bx, v3 = acc[mi][nj][3] + by;
            if (act == 1) {
                v0 = fmaxf(v0, 0.f); v1 = fmaxf(v1, 0.f);
                v2 = fmaxf(v2, 0.f); v3 = fmaxf(v3, 0.f);
            }
            if (row < M)     *(float2*)&Y[(size_t)row * Nout + col] = make_float2(v0, v1);
            if (row + 8 < M) *(float2*)&Y[(size_t)(row + 8) * Nout + col] = make_float2(v2, v3);
        }
    }
}

// ---------------- flash attention (unchanged, passing at R3) ----------------
__global__ __launch_bounds__(256) void attn_flash(
    const float* __restrict__ Qm, int sQ,
    const float* __restrict__ Km, const float* __restrict__ Vm, int sKV,
    float* __restrict__ O, float* __restrict__ stats_m, float* __restrict__ stats_l,
    int Lq, int Lk, int causal)
{
    extern __shared__ float sm[];
    float* Qt2 = sm;
    float* Kt  = sm + 4224;
    float* Ps  = sm + 6400;
    float* Vs  = sm + 10752;

    int bh = blockIdx.y;
    int b = bh >> 3, h = bh & 7;
    int i0 = blockIdx.x * 64;
    int t = threadIdx.x;
    int ty = t >> 4, tx = t & 15;
    int ri = ty * 4;
    const float scale = 0.1767766953f;

    {
        int r = t >> 2, k8 = (t & 3) * 8;
        int gi = i0 + r;
        float4 v0 = make_float4(0,0,0,0), v1 = make_float4(0,0,0,0);
        if (gi < Lq) {
            const float* qp = &Qm[(size_t)(b * Lq + gi) * sQ + h * HD + k8];
            v0 = *(const float4*)qp; v1 = *(const float4*)(qp + 4);
        }
        float vv[8] = {v0.x, v0.y, v0.z, v0.w, v1.x, v1.y, v1.z, v1.w};
        #pragma unroll
        for (int kk = 0; kk < 8; kk++)
            *(float2*)&Qt2[(k8 + kk) * 132 + 2 * r] = make_float2(vv[kk], vv[kk]);
    }

    float m[4], l[4];
    ull o2[4];
    #pragma unroll
    for (int u = 0; u < 4; u++) { m[u] = -1e30f; l[u] = 0.f; o2[u] = 0ull; }

    int nkc = (Lk + 63) >> 6;
    if (causal) { int mx = (i0 >> 6) + 1; if (mx < nkc) nkc = mx; }

    for (int kc = 0; kc < nkc; kc++) {
        __syncthreads();
        {
            int j = t >> 2, k8 = (t & 3) * 8;
            int gj = kc * 64 + j;
            float4 v0 = make_float4(0,0,0,0), v1 = make_float4(0,0,0,0);
            float4 w0 = make_float4(0,0,0,0), w1 = make_float4(0,0,0,0);
            if (gj < Lk) {
                const float* kp = &Km[(size_t)(b * Lk + gj) * sKV + h * HD + k8];
                v0 = *(const float4*)kp; v1 = *(const float4*)(kp + 4);
                const float* vp = &Vm[(size_t)(b * Lk + gj) * sKV + h * HD + k8];
                w0 = *(const float4*)vp; w1 = *(const float4*)(vp + 4);
            }
            float vv[8] = {v0.x, v0.y, v0.z, v0.w, v1.x, v1.y, v1.z, v1.w};
            #pragma unroll
            for (int kk = 0; kk < 8; kk++) Kt[(k8 + kk) * 68 + j] = vv[kk];
            *(float4*)&Vs[j * 36 + k8] = w0;
            *(float4*)&Vs[j * 36 + k8 + 4] = w1;
        }
        __syncthreads();

        ull acc2[4][2];
        #pragma unroll
        for (int u = 0; u < 4; u++) { acc2[u][0] = 0ull; acc2[u][1] = 0ull; }
        #pragma unroll
        for (int k = 0; k < 32; k++) {
            const float* qrow = &Qt2[k * 132 + 2 * ri];
            ull a0 = *(const ull*)&qrow[0];
            ull a1 = *(const ull*)&qrow[2];
            ull aa2 = *(const ull*)&qrow[4];
            ull a3 = *(const ull*)&qrow[6];
            float4 bv = *(const float4*)&Kt[k * 68 + tx * 4];
            ull b0 = ((const ull*)&bv)[0], b1 = ((const ull*)&bv)[1];
            FFMA2(acc2[0][0], a0, b0);  FFMA2(acc2[0][1], a0, b1);
            FFMA2(acc2[1][0], a1, b0);  FFMA2(acc2[1][1], a1, b1);
            FFMA2(acc2[2][0], aa2, b0); FFMA2(acc2[2][1], aa2, b1);
            FFMA2(acc2[3][0], a3, b0);  FFMA2(acc2[3][1], a3, b1);
        }

        int c0 = kc * 64 + tx * 4;
        #pragma unroll
        for (int u = 0; u < 4; u++) {
            float2 pa = *(float2*)&acc2[u][0], pb = *(float2*)&acc2[u][1];
            float s0 = pa.x * scale, s1 = pa.y * scale, s2 = pb.x * scale, s3 = pb.y * scale;
            int gi = i0 + ri + u;
            if (c0 + 0 >= Lk || (causal && c0 + 0 > gi)) s0 = -1e30f;
            if (c0 + 1 >= Lk || (causal && c0 + 1 > gi)) s1 = -1e30f;
            if (c0 + 2 >= Lk || (causal && c0 + 2 > gi)) s2 = -1e30f;
            if (c0 + 3 >= Lk || (causal && c0 + 3 > gi)) s3 = -1e30f;
            float cm = fmaxf(fmaxf(s0, s1), fmaxf(s2, s3));
            #pragma unroll
            for (int off = 8; off; off >>= 1)
                cm = fmaxf(cm, __shfl_xor_sync(0xffffffffu, cm, off));
            float mn = fmaxf(m[u], cm);
            float alpha = __expf(m[u] - mn);
            float p0 = __expf(s0 - mn), p1 = __expf(s1 - mn);
            float p2v = __expf(s2 - mn), p3 = __expf(s3 - mn);
            float rs = (p0 + p1) + (p2v + p3);
            #pragma unroll
            for (int off = 8; off; off >>= 1)
                rs += __shfl_xor_sync(0xffffffffu, rs, off);
            l[u] = l[u] * alpha + rs;
            m[u] = mn;
            ull al2; PACK2(al2, alpha);
            MUL2(o2[u], o2[u], al2);
            *(float4*)&Ps[(ri + u) * 68 + tx * 4] = make_float4(p0, p1, p2v, p3);
        }
        __syncthreads();

        #pragma unroll 4
        for (int j4 = 0; j4 < 16; j4++) {
            int j = j4 * 4;
            float4 pr[4];
            #pragma unroll
            for (int u = 0; u < 4; u++)
                pr[u] = *(const float4*)&Ps[(ri + u) * 68 + j];
            #pragma unroll
            for (int jj = 0; jj < 4; jj++) {
                ull vj = *(const ull*)&Vs[(j + jj) * 36 + 2 * tx];
                #pragma unroll
                for (int u = 0; u < 4; u++) {
                    float pv = ((const float*)&pr[u])[jj];
                    ull d; PACK2(d, pv);
                    FFMA2(o2[u], d, vj);
                }
            }
        }
    }

    #pragma unroll
    for (int u = 0; u < 4; u++) {
        int gi = i0 + ri + u;
        if (gi >= Lq) continue;
        float inv = 1.f / l[u];
        float2 ov = *(float2*)&o2[u];
        ov.x *= inv; ov.y *= inv;
        *(float2*)&O[(size_t)(b * Lq + gi) * DD + h * HD + 2 * tx] = ov;
        if (stats_m && tx == 0) {
            stats_m[(size_t)bh * Lq + gi] = m[u];
            stats_l[(size_t)bh * Lq + gi] = l[u];
        }
    }
}

// ---------------- wmean pass2 ----------------
__global__ __launch_bounds__(256) void wmean_kernel(
    const float* __restrict__ Qm, int sQ,
    const float* __restrict__ Km, int sKV,
    const float* __restrict__ stats_m, const float* __restrict__ stats_l,
    float* __restrict__ out)
{
    __shared__ float Qt2[32 * 132];
    __shared__ float Kt[32 * 68];

    int qt = blockIdx.x, b = blockIdx.y, kc = blockIdx.z;
    int i0 = qt * 64;
    int t = threadIdx.x;
    int ty = t >> 4, tx = t & 15;
    int ri = ty * 4;
    const float scale = 0.1767766953f;

    float macc[4][4];
    #pragma unroll
    for (int u = 0; u < 4; u++)
        #pragma unroll
        for (int v = 0; v < 4; v++) macc[u][v] = 0.f;

    for (int h = 0; h < HH; h++) {
        __syncthreads();
        {
            int r = t >> 2, k8 = (t & 3) * 8;
            int gi = i0 + r;
            const float* qp = &Qm[(size_t)(b * NN + gi) * sQ + h * HD + k8];
            float4 v0 = *(const float4*)qp, v1 = *(const float4*)(qp + 4);
            float vv[8] = {v0.x, v0.y, v0.z, v0.w, v1.x, v1.y, v1.z, v1.w};
            #pragma unroll
            for (int kk = 0; kk < 8; kk++)
                *(float2*)&Qt2[(k8 + kk) * 132 + 2 * r] = make_float2(vv[kk], vv[kk]);
            int gj = kc * 64 + r;
            const float* kp = &Km[(size_t)(b * NN + gj) * sKV + h * HD + k8];
            float4 w0 = *(const float4*)kp, w1 = *(const float4*)(kp + 4);
            float ww[8] = {w0.x, w0.y, w0.z, w0.w, w1.x, w1.y, w1.z, w1.w};
            #pragma unroll
            for (int kk = 0; kk < 8; kk++) Kt[(k8 + kk) * 68 + r] = ww[kk];
        }
        __syncthreads();

        ull acc2[4][2];
        #pragma unroll
        for (int u = 0; u < 4; u++) { acc2[u][0] = 0ull; acc2[u][1] = 0ull; }
        #pragma unroll
        for (int k = 0; k < 32; k++) {
            const float* qrow = &Qt2[k * 132 + 2 * ri];
            ull a0 = *(const ull*)&qrow[0];
            ull a1 = *(const ull*)&qrow[2];
            ull aa2 = *(const ull*)&qrow[4];
            ull a3 = *(const ull*)&qrow[6];
            float4 bv = *(const float4*)&Kt[k * 68 + tx * 4];
            ull b0 = ((const ull*)&bv)[0], b1 = ((const ull*)&bv)[1];
            FFMA2(acc2[0][0], a0, b0);  FFMA2(acc2[0][1], a0, b1);
            FFMA2(acc2[1][0], a1, b0);  FFMA2(acc2[1][1], a1, b1);
            FFMA2(acc2[2][0], aa2, b0); FFMA2(acc2[2][1], aa2, b1);
            FFMA2(acc2[3][0], a3, b0);  FFMA2(acc2[3][1], a3, b1);
        }

        int c0 = kc * 64 + tx * 4;
        #pragma unroll
        for (int u = 0; u < 4; u++) {
            int gi = i0 + ri + u;
            float mrow = stats_m[((size_t)(b * HH + h)) * NN + gi];
            float linv = 1.f / stats_l[((size_t)(b * HH + h)) * NN + gi];
            float2 pa = *(float2*)&acc2[u][0], pb = *(float2*)&acc2[u][1];
            float s[4] = {pa.x, pa.y, pb.x, pb.y};
            #pragma unroll
            for (int v = 0; v < 4; v++) {
                if (c0 + v <= gi)
                    macc[u][v] += __expf(s[v] * scale - mrow) * linv;
            }
        }
    }

    #pragma unroll
    for (int u = 0; u < 4; u++) {
        int gi = i0 + ri + u;
        float4 ov = make_float4(macc[u][0] * 0.125f, macc[u][1] * 0.125f,
                                macc[u][2] * 0.125f, macc[u][3] * 0.125f);
        *(float4*)&out[((size_t)(b * NN) + gi) * NN + kc * 64 + tx * 4] = ov;
    }
}

// ---------------- small kernels ----------------

__global__ void softmax_kernel(const float* __restrict__ src, float* __restrict__ dst, int L)
{
    size_t row = blockIdx.x;
    const float* p = src + row * (size_t)L;
    float* o = dst + row * (size_t)L;
    int t = threadIdx.x;
    float vals[8];
    int cnt = (L + 255) / 256;
    float mx = -1e30f;
    for (int i = 0; i < cnt; i++) {
        int idx = t + i * 256;
        vals[i] = (idx < L) ? p[idx] : -1e30f;
        mx = fmaxf(mx, vals[i]);
    }
    __shared__ float red[256];
    red[t] = mx; __syncthreads();
    for (int s = 128; s > 0; s >>= 1) { if (t < s) red[t] = fmaxf(red[t], red[t + s]); __syncthreads(); }
    mx = red[0]; __syncthreads();
    float sum = 0.f;
    for (int i = 0; i < cnt; i++) {
        int idx = t + i * 256;
        if (idx < L) { vals[i] = expf(vals[i] - mx); sum += vals[i]; }
    }
    red[t] = sum; __syncthreads();
    for (int s = 128; s > 0; s >>= 1) { if (t < s) red[t] += red[t + s]; __syncthreads(); }
    float inv = 1.f / red[0];
    for (int i = 0; i < cnt; i++) {
        int idx = t + i * 256;
        if (idx < L) o[idx] = vals[i] * inv;
    }
}

__global__ void add_ln_kernel(const float* __restrict__ a, const float* __restrict__ b,
                              const float* __restrict__ c,
                              const float* __restrict__ g, const float* __restrict__ bet,
                              float* __restrict__ out)
{
    size_t row = blockIdx.x;
    int t = threadIdx.x;
    float x = a[row * DD + t] + b[row * DD + t];
    if (c) x += c[row * DD + t];
    __shared__ float red[256];
    red[t] = x; __syncthreads();
    for (int s = 128; s > 0; s >>= 1) { if (t < s) red[t] += red[t + s]; __syncthreads(); }
    float mean = red[0] * (1.f / DD); __syncthreads();
    float d = x - mean;
    red[t] = d * d; __syncthreads();
    for (int s = 128; s > 0; s >>= 1) { if (t < s) red[t] += red[t + s]; __syncthreads(); }
    float var = red[0] * (1.f / DD);
    out[row * DD + t] = d * rsqrtf(var + 1e-5f) * g[t] + bet[t];
}

__global__ void embed_kernel(const int* __restrict__ q, const int* __restrict__ r,
                             const int* __restrict__ qry,
                             const float* __restrict__ M_emb, const float* __restrict__ E_emb,
                             const float* __restrict__ P,
                             float* __restrict__ M, float* __restrict__ E)
{
    int row = blockIdx.x; int t = threadIdx.x;
    int n = row % NN;
    int x = q[row] + NQ * r[row];
    M[(size_t)row * DD + t] = M_emb[(size_t)x * DD + t] + P[n * DD + t];
    E[(size_t)row * DD + t] = E_emb[(size_t)qry[row] * DD + t];
}

__global__ void gather_skill_kernel(const int* __restrict__ q, const float* __restrict__ rep,
                                    float* __restrict__ out)
{
    int row = blockIdx.x; int t = threadIdx.x;
    out[(size_t)row * DD + t] = rep[(size_t)q[row] * DD + t];
}

__global__ void gather_loc_kernel(const float* __restrict__ Sb, float* __restrict__ loc)
{
    int row = blockIdx.x; int t = threadIdx.x;
    int b = row / LWW, j = row % LWW;
    loc[(size_t)row * DD + t] = Sb[((size_t)(b * NN + NN - LWW + j)) * DD + t];
}

__global__ void scatter_loc_kernel(const float* __restrict__ locout, float* __restrict__ Sl)
{
    int row = blockIdx.x; int t = threadIdx.x;
    int b = row / LWW, j = row % LWW;
    Sl[((size_t)(b * NN + NN - LWW + j)) * DD + t] = locout[(size_t)row * DD + t];
}

__global__ void fill_zero_kernel(float* __restrict__ p, size_t n)
{
    size_t i = (size_t)blockIdx.x * 256 + threadIdx.x;
    if (i < n) p[i] = 0.f;
}

__global__ void sum6_kernel(const float* a, const float* b, const float* c,
                            const float* d, const float* e, const float* f,
                            float* __restrict__ out, size_t n)
{
    size_t i = (size_t)blockIdx.x * 256 + threadIdx.x;
    if (i < n) out[i] = a[i] + b[i] + c[i] + d[i] + e[i] + f[i];
}

__global__ void pred_kernel(const float* __restrict__ F, const float* __restrict__ w,
                            const float* __restrict__ b, float* __restrict__ out)
{
    size_t row = blockIdx.x;
    int t = threadIdx.x;
    float v = F[row * DD + t] * w[t];
    __shared__ float red[256];
    red[t] = v; __syncthreads();
    for (int s = 128; s > 0; s >>= 1) { if (t < s) red[t] += red[t + s]; __syncthreads(); }
    if (t == 0) out[row] = 1.f / (1.f + expf(-(red[0] + b[0])));
}

// ---------------- host orchestration ----------------

static void g128(const float* X, const float* W, const float* bias, float* Y,
                 int M, int K, int Nout, int act = 0,
                 int batch = 1, long long sX = 0, long long sW = 0, long long sY = 0)
{
    dim3 grid(Nout / 128, (M + 127) / 128, batch);
    mma_gemm<<<grid, 256>>>(X, W, bias, Y, M, K, Nout, act, sX, sW, sY);
}

static void run_attn(const float* Q, int sQ, const float* K, const float* V, int sKV,
                     float* O, float* sm_, float* sl_, int Lq, int Lk, int causal)
{
    static bool attr_set = false;
    if (!attr_set) {
        cudaFuncSetAttribute(attn_flash, cudaFuncAttributeMaxDynamicSharedMemorySize, 64 * 1024);
        attr_set = true;
    }
    dim3 grid((Lq + 63) / 64, BB * HH);
    attn_flash<<<grid, 256, 52224>>>(Q, sQ, K, V, sKV, O, sm_, sl_, Lq, Lk, causal);
}

#define GETSYM(var, symbol) float* var; { void* _p = nullptr; cudaGetSymbolAddress(&_p, symbol); var = (float*)_p; }

extern "C" void kernel_launch(void* const* d_in, const int* in_sizes, int n_in,
                              void* d_out, int out_size)
{
    const int*   q    = (const int*)d_in[0];
    const int*   r    = (const int*)d_in[1];
    const int*   qry  = (const int*)d_in[2];
    const float* M_emb = (const float*)d_in[3];
    const float* E_emb = (const float*)d_in[4];
    const float* P     = (const float*)d_in[5];
    const float* attn_in_w  = (const float*)d_in[6];
    const float* attn_in_b  = (const float*)d_in[7];
    const float* attn_out_w = (const float*)d_in[8];
    const float* attn_out_b = (const float*)d_in[9];
    const float* skill_cw   = (const float*)d_in[10];
    const float* skill_pw   = (const float*)d_in[11];
    const float* skill_pb   = (const float*)d_in[12];
    const float* skill_ew   = (const float*)d_in[13];
    const float* skill_eb   = (const float*)d_in[14];
    const float* ffn_w1 = (const float*)d_in[15];
    const float* ffn_b1 = (const float*)d_in[16];
    const float* ffn_w2 = (const float*)d_in[17];
    const float* ffn_b2 = (const float*)d_in[18];
    const float* ln1_g  = (const float*)d_in[19];
    const float* ln1_b  = (const float*)d_in[20];
    const float* ln2_g  = (const float*)d_in[21];
    const float* ln2_b  = (const float*)d_in[22];
    const float* pred_w = (const float*)d_in[23];
    const float* pred_b = (const float*)d_in[24];

    float* out_p = (float*)d_out;
    float* out_attn = out_p + BB * NN;

    GETSYM(pM, g_M);   GETSYM(pE, g_E);   GETSYM(pSbase, g_Sbase); GETSYM(pSlocal, g_Slocal);
    GETSYM(pSsg, g_Ssg); GETSYM(pSglob, g_Sglob); GETSYM(pSbl, g_Sbl); GETSYM(pSsgl, g_Ssgl);
    GETSYM(pQKV, g_QKV); GETSYM(pQb, g_Qb); GETSYM(pKV, g_KV); GETSYM(pOh, g_Oh); GETSYM(pT, g_T);
    GETSYM(pSW, g_SW); GETSYM(psrep, g_srep); GETSYM(psgr, g_sgr);
    GETSYM(psg1, g_sg1); GETSYM(psg2, g_sg2);
    GETSYM(ploc, g_loc); GETSYM(plocout, g_locout);
    GETSYM(psum, g_sum); GETSYM(pf1, g_f1); GETSYM(pF, g_F);
    GETSYM(psm, g_sm); GETSYM(psl, g_sl);

    const size_t BND = (size_t)BB * NN * DD;
    const int MR = BB * NN;
    const int W3 = 3 * DD * DD, B3 = 3 * DD, W1 = DD * DD;

    // 1. embeddings
    embed_kernel<<<BB * NN, 256>>>(q, r, qry, M_emb, E_emb, P, pM, pE);

    // 2. attn0: q=E, kv=M, causal; flash saves per-row stats
    g128(pE, attn_in_w, attn_in_b, pQb, MR, DD, DD);
    g128(pM, attn_in_w + DD * DD, attn_in_b + DD, pKV, MR, DD, 2 * DD);
    run_attn(pQb, DD, pKV, pKV + DD, 2 * DD, pOh, psm, psl, NN, NN, 1);
    wmean_kernel<<<dim3(8, 32, 8), 256>>>(pQb, DD, pKV, 2 * DD, psm, psl, out_attn);
    g128(pOh, attn_out_w, attn_out_b, pT, MR, DD, DD);

    // 3. S_base = LN(attn0 + M + E)
    add_ln_kernel<<<BB * NN, 256>>>(pT, pM, pE, ln1_g, ln1_b, pSbase);

    // 4. local attention on last LW rows
    gather_loc_kernel<<<BB * LWW, 256>>>(pSbase, ploc);
    g128(ploc, attn_in_w + 1 * W3, attn_in_b + 1 * B3, pQKV, BB * LWW, DD, 3 * DD);
    run_attn(pQKV, 3 * DD, pQKV + DD, pQKV + 2 * DD, 3 * DD, pOh, nullptr, nullptr, LWW, LWW, 1);
    g128(pOh, attn_out_w + 1 * W1, attn_out_b + 1 * DD, plocout, BB * LWW, DD, DD);
    fill_zero_kernel<<<(unsigned)((BND + 255) / 256), 256>>>(pSlocal, BND);
    scatter_loc_kernel<<<BB * LWW, 256>>>(plocout, pSlocal);

    // 5. skill path
    softmax_kernel<<<NQ, 256>>>(skill_cw, pSW, NQ);
    g128(pSW, skill_pw, skill_pb, psrep, NQ, NQ, DD);
    gather_skill_kernel<<<BB * NN, 256>>>(q, psrep, psgr);

    // 6. S_sg1[b] = S_base[b] @ sgr[b]^T
    g128(pSbase, psgr, nullptr, psg1, NN, DD, NN, 0, BB,
         (long long)NN * DD, (long long)NN * DD, (long long)NN * NN);

    // 7. S_sg2 = S_sg1 @ skill_to_embed_w^T + b
    g128(psg1, skill_ew, skill_eb, psg2, MR, NN, DD);

    // 8. attn2 (self, no mask) on S_sg2
    g128(psg2, attn_in_w + 2 * W3, attn_in_b + 2 * B3, pQKV, MR, DD, 3 * DD);
    run_attn(pQKV, 3 * DD, pQKV + DD, pQKV + 2 * DD, 3 * DD, pOh, nullptr, nullptr, NN, NN, 0);
    g128(pOh, attn_out_w + 2 * W1, attn_out_b + 2 * DD, pSsg, MR, DD, DD);

    // 9. attn3 (self, causal) on S_base
    g128(pSbase, attn_in_w + 3 * W3, attn_in_b + 3 * B3, pQKV, MR, DD, 3 * DD);
    run_attn(pQKV, 3 * DD, pQKV + DD, pQKV + 2 * DD, 3 * DD, pOh, nullptr, nullptr, NN, NN, 1);
    g128(pOh, attn_out_w + 3 * W1, attn_out_b + 3 * DD, pSglob, MR, DD, DD);

    // 10. attn4: q=S_base, kv=S_local, no mask
    g128(pSbase, attn_in_w + 4 * W3, attn_in_b + 4 * B3, pQb, MR, DD, DD);
    g128(pSlocal, attn_in_w + 4 * W3 + DD * DD, attn_in_b + 4 * B3 + DD, pKV, MR, DD, 2 * DD);
    run_attn(pQb, DD, pKV, pKV + DD, 2 * DD, pOh, nullptr, nullptr, NN, NN, 0);
    g128(pOh, attn_out_w + 4 * W1, attn_out_b + 4 * DD, pSbl, MR, DD, DD);

    // 11. attn5: q=S_sg, kv=S_glob, no mask
    g128(pSsg, attn_in_w + 5 * W3, attn_in_b + 5 * B3, pQb, MR, DD, DD);
    g128(pSglob, attn_in_w + 5 * W3 + DD * DD, attn_in_b + 5 * B3 + DD, pKV, MR, DD, 2 * DD);
    run_attn(pQb, DD, pKV, pKV + DD, 2 * DD, pOh, nullptr, nullptr, NN, NN, 0);
    g128(pOh, attn_out_w + 5 * W1, attn_out_b + 5 * DD, pSsgl, MR, DD, DD);

    // 12. S = sum of six streams
    sum6_kernel<<<(unsigned)((BND + 255) / 256), 256>>>(pSbase, pSlocal, pSsg, pSglob, pSbl, pSsgl,
                                                        psum, BND);

    // 13. FFN + residual + LN2
    g128(psum, ffn_w1, ffn_b1, pf1, MR, DD, DD, 1);
    g128(pf1, ffn_w2, ffn_b2, pT, MR, DD, DD);
    add_ln_kernel<<<BB * NN, 256>>>(pT, psum, nullptr, ln2_g, ln2_b, pF);

    // 14. prediction head
    pred_kernel<<<BB * NN, 256>>>(pF, pred_w, pred_b, out_p);
}

// round 6
// speedup vs baseline: 4.2752x; 1.3556x over previous
#include <cuda_runtime.h>
#include <math.h>
#include <stdint.h>

#define BB 32
#define NN 512
#define DD 256
#define HH 8
#define HD 32
#define LWW 25
#define NQ 2048

typedef unsigned long long ull;
#define FFMA2(d, a, b) asm("fma.rn.f32x2 %0, %1, %2, %3;" : "=l"(d) : "l"(a), "l"(b), "l"(d))
#define MUL2(d, a, b)  asm("mul.rn.f32x2 %0, %1, %2;" : "=l"(d) : "l"(a), "l"(b))
#define PACK2(d, s)    asm("mov.b64 %0, {%1, %1};" : "=l"(d) : "f"(s))

#define CVT_TF32(u, f) asm("cvt.rna.tf32.f32 %0, %1;" : "=r"(u) : "f"(f))
#define MMA_TF32(c, a0, a1, a2, a3, b0, b1) \
    asm volatile("mma.sync.aligned.m16n8k8.row.col.f32.tf32.tf32.f32 " \
        "{%0,%1,%2,%3}, {%4,%5,%6,%7}, {%8,%9}, {%0,%1,%2,%3};" \
        : "+f"((c)[0]), "+f"((c)[1]), "+f"((c)[2]), "+f"((c)[3]) \
        : "r"(a0), "r"(a1), "r"(a2), "r"(a3), "r"(b0), "r"(b1))

// ---------------- scratch ----------------
__device__ float g_M[BB*NN*DD];
__device__ float g_E[BB*NN*DD];
__device__ float g_Sbase[BB*NN*DD];
__device__ float g_Ssg[BB*NN*DD];
__device__ float g_Sglob[BB*NN*DD];
__device__ float g_Sbl[BB*NN*DD];
__device__ float g_Ssgl[BB*NN*DD];
__device__ float g_QKV[BB*NN*3*DD];
__device__ float g_Qb[BB*NN*DD];
__device__ float g_KV[BB*NN*2*DD];
__device__ float g_Oh[BB*NN*DD];
__device__ float g_T[BB*NN*DD];
__device__ float g_SW[NQ*NQ];
__device__ float g_srep[NQ*DD];
__device__ float g_sgr[BB*NN*DD];
__device__ float g_sg1[BB*NN*NN];
__device__ float g_sg2[BB*NN*DD];
__device__ float g_loc[BB*LWW*DD];
__device__ float g_locout[BB*LWW*DD];
__device__ float g_sum[BB*NN*DD];
__device__ float g_f1[BB*NN*DD];
__device__ float g_F[BB*NN*DD];
__device__ float g_sm[BB*HH*NN];
__device__ float g_sl[BB*HH*NN];

// ================= HMMA tf32 GEMM (unchanged from R5) =================
__global__ __launch_bounds__(256) void mma_gemm(
    const float* __restrict__ X, const float* __restrict__ W,
    const float* __restrict__ bias, float* __restrict__ Y,
    int M, int K, int Nout, int act,
    long long sX, long long sW, long long sY)
{
    __shared__ float As[128 * 36];
    __shared__ float Bs[128 * 36];

    X += (size_t)blockIdx.z * sX;
    W += (size_t)blockIdx.z * sW;
    Y += (size_t)blockIdx.z * sY;

    int t = threadIdx.x, lane = t & 31, warp = t >> 5;
    int wm = warp & 1, wn = warp >> 1;
    int m0 = blockIdx.y * 128, n0 = blockIdx.x * 128;
    int mbase = wm * 64, nbase = wn * 32;
    int lq = lane >> 2, lr = lane & 3;

    float acc[4][4][4];
    #pragma unroll
    for (int mi = 0; mi < 4; mi++)
        #pragma unroll
        for (int nj = 0; nj < 4; nj++)
            #pragma unroll
            for (int c = 0; c < 4; c++) acc[mi][nj][c] = 0.f;

    for (int k0 = 0; k0 < K; k0 += 32) {
        __syncthreads();
        #pragma unroll
        for (int l = 0; l < 4; l++) {
            int s = t + l * 256;
            int r = s >> 3, c4 = s & 7;
            int gm = m0 + r;
            float4 v = make_float4(0.f, 0.f, 0.f, 0.f);
            if (gm < M) v = *(const float4*)&X[(size_t)gm * K + k0 + c4 * 4];
            uint32_t ua[4];
            CVT_TF32(ua[0], v.x); CVT_TF32(ua[1], v.y);
            CVT_TF32(ua[2], v.z); CVT_TF32(ua[3], v.w);
            int gn = n0 + r;
            float4 w = make_float4(0.f, 0.f, 0.f, 0.f);
            if (gn < Nout) w = *(const float4*)&W[(size_t)gn * K + k0 + c4 * 4];
            uint32_t ub[4];
            CVT_TF32(ub[0], w.x); CVT_TF32(ub[1], w.y);
            CVT_TF32(ub[2], w.z); CVT_TF32(ub[3], w.w);
            #pragma unroll
            for (int j = 0; j < 4; j++) {
                int jj = (j + lane) & 3;
                As[r * 36 + c4 * 4 + jj] = __uint_as_float(ua[jj]);
                Bs[r * 36 + c4 * 4 + jj] = __uint_as_float(ub[jj]);
            }
        }
        __syncthreads();

        #pragma unroll
        for (int ks = 0; ks < 4; ks++) {
            int kk = ks * 8;
            uint32_t a[4][4], b[4][2];
            #pragma unroll
            for (int mi = 0; mi < 4; mi++) {
                int row = mbase + mi * 16 + lq;
                a[mi][0] = __float_as_uint(As[row * 36 + kk + lr]);
                a[mi][1] = __float_as_uint(As[(row + 8) * 36 + kk + lr]);
                a[mi][2] = __float_as_uint(As[row * 36 + kk + lr + 4]);
                a[mi][3] = __float_as_uint(As[(row + 8) * 36 + kk + lr + 4]);
            }
            #pragma unroll
            for (int nj = 0; nj < 4; nj++) {
                int nr = nbase + nj * 8 + lq;
                b[nj][0] = __float_as_uint(Bs[nr * 36 + kk + lr]);
                b[nj][1] = __float_as_uint(Bs[nr * 36 + kk + lr + 4]);
            }
            #pragma unroll
            for (int mi = 0; mi < 4; mi++)
                #pragma unroll
                for (int nj = 0; nj < 4; nj++)
                    MMA_TF32(acc[mi][nj], a[mi][0], a[mi][1], a[mi][2], a[mi][3],
                             b[nj][0], b[nj][1]);
        }
    }

    #pragma unroll
    for (int nj = 0; nj < 4; nj++) {
        int col = n0 + nbase + nj * 8 + 2 * lr;
        float bx = 0.f, by = 0.f;
        if (bias) { bx = bias[col]; by = bias[col + 1]; }
        #pragma unroll
        for (int mi = 0; mi < 4; mi++) {
            int row = m0 + mbase + mi * 16 + lq;
            float v0 = acc[mi][nj][0] + bx, v1 = acc[mi][nj][1] + by;
            float v2 = acc[mi][nj][2] + bx, v3 = acc[mi][nj][3] + by;
            if (act == 1) {
                v0 = fmaxf(v0, 0.f); v1 = fmaxf(v1, 0.f);
                v2 = fmaxf(v2, 0.f); v3 = fmaxf(v3, 0.f);
            }
            if (row < M)     *(float2*)&Y[(size_t)row * Nout + col] = make_float2(v0, v1);
            if (row + 8 < M) *(float2*)&Y[(size_t)(row + 8) * Nout + col] = make_float2(v2, v3);
        }
    }
}

// ================= flash attention, tensor-core (tf32 MMA) =================
// grid ((Lq+63)/64, B*H), block 128 (4 warps; warp = 16 q rows).
__global__ __launch_bounds__(128) void attn_flash(
    const float* __restrict__ Qm, int sQ,
    const float* __restrict__ Km, const float* __restrict__ Vm, int sKV,
    float* __restrict__ O, float* __restrict__ stats_m, float* __restrict__ stats_l,
    int Lq, int Lk, int causal)
{
    __shared__ float Qs[64 * 36];
    __shared__ float Kt[32 * 72];
    __shared__ float Vs[64 * 40];
    __shared__ float Ps[64 * 68];

    int bh = blockIdx.y, b = bh >> 3, h = bh & 7;
    int i0 = blockIdx.x * 64;
    int t = threadIdx.x, lane = t & 31, warp = t >> 5;
    int lq = lane >> 2, lr = lane & 3;
    const float scale = 0.1767766953f;

    // load Q tile (tf32 bits in Qs[row][d])
    {
        int r = t & 63, half = t >> 6;
        int gi = i0 + r;
        float buf[16];
        #pragma unroll
        for (int i = 0; i < 16; i++) buf[i] = 0.f;
        if (gi < Lq) {
            const float* qp = &Qm[(size_t)(b * Lq + gi) * sQ + h * HD + half * 16];
            #pragma unroll
            for (int i = 0; i < 4; i++)
                *(float4*)&buf[i * 4] = *(const float4*)&qp[i * 4];
        }
        #pragma unroll
        for (int i = 0; i < 16; i++) {
            uint32_t u; CVT_TF32(u, buf[i]);
            Qs[r * 36 + half * 16 + i] = __uint_as_float(u);
        }
    }

    float m0 = -1e30f, m1 = -1e30f, l0 = 0.f, l1 = 0.f;
    float o[4][4];
    #pragma unroll
    for (int i = 0; i < 4; i++)
        #pragma unroll
        for (int j = 0; j < 4; j++) o[i][j] = 0.f;

    int gi0 = i0 + warp * 16 + lq, gi1 = gi0 + 8;
    int nkc = (Lk + 63) >> 6;
    if (causal) { int mx = (i0 >> 6) + 1; if (mx < nkc) nkc = mx; }

    for (int kc = 0; kc < nkc; kc++) {
        __syncthreads();
        // K (transposed tf32) + V (row-major tf32)
        {
            int key = t & 63, half = t >> 6;
            int gj = kc * 64 + key;
            float kb[16], vb[16];
            #pragma unroll
            for (int i = 0; i < 16; i++) { kb[i] = 0.f; vb[i] = 0.f; }
            if (gj < Lk) {
                const float* kp = &Km[(size_t)(b * Lk + gj) * sKV + h * HD + half * 16];
                const float* vp = &Vm[(size_t)(b * Lk + gj) * sKV + h * HD + half * 16];
                #pragma unroll
                for (int i = 0; i < 4; i++) {
                    *(float4*)&kb[i * 4] = *(const float4*)&kp[i * 4];
                    *(float4*)&vb[i * 4] = *(const float4*)&vp[i * 4];
                }
            }
            #pragma unroll
            for (int i = 0; i < 16; i++) {
                uint32_t uk, uv;
                CVT_TF32(uk, kb[i]); CVT_TF32(uv, vb[i]);
                Kt[(half * 16 + i) * 72 + key] = __uint_as_float(uk);
                Vs[key * 40 + half * 16 + i] = __uint_as_float(uv);
            }
        }
        __syncthreads();

        // scores: warp computes 16x64 via MMA
        uint32_t a[4][4];
        #pragma unroll
        for (int ks = 0; ks < 4; ks++) {
            int rb = (warp * 16 + lq) * 36 + ks * 8;
            a[ks][0] = __float_as_uint(Qs[rb + lr]);
            a[ks][1] = __float_as_uint(Qs[rb + 8 * 36 + lr]);
            a[ks][2] = __float_as_uint(Qs[rb + lr + 4]);
            a[ks][3] = __float_as_uint(Qs[rb + 8 * 36 + lr + 4]);
        }
        float sc[8][4];
        #pragma unroll
        for (int nt = 0; nt < 8; nt++) {
            #pragma unroll
            for (int c = 0; c < 4; c++) sc[nt][c] = 0.f;
            #pragma unroll
            for (int ks = 0; ks < 4; ks++) {
                uint32_t b0 = __float_as_uint(Kt[(ks * 8 + lr) * 72 + nt * 8 + lq]);
                uint32_t b1 = __float_as_uint(Kt[(ks * 8 + lr + 4) * 72 + nt * 8 + lq]);
                MMA_TF32(sc[nt], a[ks][0], a[ks][1], a[ks][2], a[ks][3], b0, b1);
            }
        }

        // mask + scale + row maxes
        float r0mx = -1e30f, r1mx = -1e30f;
        #pragma unroll
        for (int nt = 0; nt < 8; nt++) {
            int c0 = kc * 64 + nt * 8 + lr * 2;
            float s0 = sc[nt][0] * scale, s1 = sc[nt][1] * scale;
            float s2 = sc[nt][2] * scale, s3 = sc[nt][3] * scale;
            if (c0 + 0 >= Lk || (causal && c0 + 0 > gi0)) s0 = -1e30f;
            if (c0 + 1 >= Lk || (causal && c0 + 1 > gi0)) s1 = -1e30f;
            if (c0 + 0 >= Lk || (causal && c0 + 0 > gi1)) s2 = -1e30f;
            if (c0 + 1 >= Lk || (causal && c0 + 1 > gi1)) s3 = -1e30f;
            sc[nt][0] = s0; sc[nt][1] = s1; sc[nt][2] = s2; sc[nt][3] = s3;
            r0mx = fmaxf(r0mx, fmaxf(s0, s1));
            r1mx = fmaxf(r1mx, fmaxf(s2, s3));
        }
        #pragma unroll
        for (int off = 1; off < 4; off <<= 1) {
            r0mx = fmaxf(r0mx, __shfl_xor_sync(0xffffffffu, r0mx, off));
            r1mx = fmaxf(r1mx, __shfl_xor_sync(0xffffffffu, r1mx, off));
        }
        float mn0 = fmaxf(m0, r0mx), mn1 = fmaxf(m1, r1mx);
        float alpha0 = __expf(m0 - mn0), alpha1 = __expf(m1 - mn1);
        float rs0 = 0.f, rs1 = 0.f;
        #pragma unroll
        for (int nt = 0; nt < 8; nt++) {
            float p0 = __expf(sc[nt][0] - mn0), p1 = __expf(sc[nt][1] - mn0);
            float p2 = __expf(sc[nt][2] - mn1), p3 = __expf(sc[nt][3] - mn1);
            rs0 += p0 + p1; rs1 += p2 + p3;
            uint32_t u0, u1, u2, u3;
            CVT_TF32(u0, p0); CVT_TF32(u1, p1); CVT_TF32(u2, p2); CVT_TF32(u3, p3);
            *(float2*)&Ps[(warp * 16 + lq) * 68 + nt * 8 + lr * 2] =
                make_float2(__uint_as_float(u0), __uint_as_float(u1));
            *(float2*)&Ps[(warp * 16 + lq + 8) * 68 + nt * 8 + lr * 2] =
                make_float2(__uint_as_float(u2), __uint_as_float(u3));
        }
        #pragma unroll
        for (int off = 1; off < 4; off <<= 1) {
            rs0 += __shfl_xor_sync(0xffffffffu, rs0, off);
            rs1 += __shfl_xor_sync(0xffffffffu, rs1, off);
        }
        l0 = l0 * alpha0 + rs0; l1 = l1 * alpha1 + rs1;
        m0 = mn0; m1 = mn1;
        #pragma unroll
        for (int nt2 = 0; nt2 < 4; nt2++) {
            o[nt2][0] *= alpha0; o[nt2][1] *= alpha0;
            o[nt2][2] *= alpha1; o[nt2][3] *= alpha1;
        }
        __syncwarp();

        // PV: 16x32 per warp, contraction over 64 keys
        #pragma unroll
        for (int ks = 0; ks < 8; ks++) {
            int rb = (warp * 16 + lq) * 68 + ks * 8;
            uint32_t pa0 = __float_as_uint(Ps[rb + lr]);
            uint32_t pa1 = __float_as_uint(Ps[rb + 8 * 68 + lr]);
            uint32_t pa2 = __float_as_uint(Ps[rb + lr + 4]);
            uint32_t pa3 = __float_as_uint(Ps[rb + 8 * 68 + lr + 4]);
            #pragma unroll
            for (int nt2 = 0; nt2 < 4; nt2++) {
                uint32_t b0 = __float_as_uint(Vs[(ks * 8 + lr) * 40 + nt2 * 8 + lq]);
                uint32_t b1 = __float_as_uint(Vs[(ks * 8 + lr + 4) * 40 + nt2 * 8 + lq]);
                MMA_TF32(o[nt2], pa0, pa1, pa2, pa3, b0, b1);
            }
        }
        __syncwarp();
    }

    // epilogue
    float inv0 = 1.f / l0, inv1 = 1.f / l1;
    if (gi0 < Lq) {
        float* orow = &O[(size_t)(b * Lq + gi0) * DD + h * HD];
        #pragma unroll
        for (int nt2 = 0; nt2 < 4; nt2++)
            *(float2*)&orow[nt2 * 8 + lr * 2] = make_float2(o[nt2][0] * inv0, o[nt2][1] * inv0);
        if (stats_m && lr == 0) {
            stats_m[(size_t)bh * Lq + gi0] = m0;
            stats_l[(size_t)bh * Lq + gi0] = l0;
        }
    }
    if (gi1 < Lq) {
        float* orow = &O[(size_t)(b * Lq + gi1) * DD + h * HD];
        #pragma unroll
        for (int nt2 = 0; nt2 < 4; nt2++)
            *(float2*)&orow[nt2 * 8 + lr * 2] = make_float2(o[nt2][2] * inv1, o[nt2][3] * inv1);
        if (stats_m && lr == 0) {
            stats_m[(size_t)bh * Lq + gi1] = m1;
            stats_l[(size_t)bh * Lq + gi1] = l1;
        }
    }
}

// ================= attn4 analytic: 25 real keys + constant bias key x487 =================
// grid (NN/64, B*H), block 64. KVloc: (B*LW) x 512 rows (K [0,256), V [256,512)).
__global__ __launch_bounds__(64) void attn_bl_kernel(
    const float* __restrict__ Qm,
    const float* __restrict__ KVloc,
    const float* __restrict__ inb,   // attn_in_b row 4 (3D floats)
    float* __restrict__ O)
{
    __shared__ float Ks[LWW][HD + 1], Vsm[LWW][HD + 1], kb[HD], vb[HD];
    int bh = blockIdx.y, b = bh >> 3, h = bh & 7;
    int i0 = blockIdx.x * 64;
    int t = threadIdx.x;
    const float scale = 0.1767766953f;

    for (int i = t; i < LWW * HD; i += 64) {
        int rr = i / HD, dd = i % HD;
        Ks[rr][dd]  = KVloc[(size_t)(b * LWW + rr) * 512 + h * HD + dd];
        Vsm[rr][dd] = KVloc[(size_t)(b * LWW + rr) * 512 + 256 + h * HD + dd];
    }
    if (t < HD) { kb[t] = inb[DD + h * HD + t]; vb[t] = inb[2 * DD + h * HD + t]; }
    __syncthreads();

    int gi = i0 + t;
    float qv[HD];
    const float* qp = &Qm[(size_t)(b * NN + gi) * DD + h * HD];
    #pragma unroll
    for (int d = 0; d < HD; d++) qv[d] = qp[d];

    float s0 = 0.f;
    #pragma unroll
    for (int d = 0; d < HD; d++) s0 = fmaf(qv[d], kb[d], s0);
    s0 *= scale;
    float s[LWW];
    float mx = s0;
    #pragma unroll
    for (int j = 0; j < LWW; j++) {
        float acc = 0.f;
        #pragma unroll
        for (int d = 0; d < HD; d++) acc = fmaf(qv[d], Ks[j][d], acc);
        s[j] = acc * scale;
        mx = fmaxf(mx, s[j]);
    }
    float e0 = __expf(s0 - mx) * (float)(NN - LWW);
    float denom = e0;
    float ov[HD];
    #pragma unroll
    for (int d = 0; d < HD; d++) ov[d] = e0 * vb[d];
    #pragma unroll
    for (int j = 0; j < LWW; j++) {
        float ej = __expf(s[j] - mx);
        denom += ej;
        #pragma unroll
        for (int d = 0; d < HD; d++) ov[d] = fmaf(ej, Vsm[j][d], ov[d]);
    }
    float inv = 1.f / denom;
    float* orow = &O[(size_t)(b * NN + gi) * DD + h * HD];
    #pragma unroll
    for (int d = 0; d < HD; d++) orow[d] = ov[d] * inv;
}

// ---------------- wmean pass2 (unchanged from R5) ----------------
__global__ __launch_bounds__(256) void wmean_kernel(
    const float* __restrict__ Qm, int sQ,
    const float* __restrict__ Km, int sKV,
    const float* __restrict__ stats_m, const float* __restrict__ stats_l,
    float* __restrict__ out)
{
    __shared__ float Qt2[32 * 132];
    __shared__ float Kt[32 * 68];

    int qt = blockIdx.x, b = blockIdx.y, kc = blockIdx.z;
    int i0 = qt * 64;
    int t = threadIdx.x;
    int ty = t >> 4, tx = t & 15;
    int ri = ty * 4;
    const float scale = 0.1767766953f;

    float macc[4][4];
    #pragma unroll
    for (int u = 0; u < 4; u++)
        #pragma unroll
        for (int v = 0; v < 4; v++) macc[u][v] = 0.f;

    for (int h = 0; h < HH; h++) {
        __syncthreads();
        {
            int r = t >> 2, k8 = (t & 3) * 8;
            int gi = i0 + r;
            const float* qp = &Qm[(size_t)(b * NN + gi) * sQ + h * HD + k8];
            float4 v0 = *(const float4*)qp, v1 = *(const float4*)(qp + 4);
            float vv[8] = {v0.x, v0.y, v0.z, v0.w, v1.x, v1.y, v1.z, v1.w};
            #pragma unroll
            for (int kk = 0; kk < 8; kk++)
                *(float2*)&Qt2[(k8 + kk) * 132 + 2 * r] = make_float2(vv[kk], vv[kk]);
            int gj = kc * 64 + r;
            const float* kp = &Km[(size_t)(b * NN + gj) * sKV + h * HD + k8];
            float4 w0 = *(const float4*)kp, w1 = *(const float4*)(kp + 4);
            float ww[8] = {w0.x, w0.y, w0.z, w0.w, w1.x, w1.y, w1.z, w1.w};
            #pragma unroll
            for (int kk = 0; kk < 8; kk++) Kt[(k8 + kk) * 68 + r] = ww[kk];
        }
        __syncthreads();

        ull acc2[4][2];
        #pragma unroll
        for (int u = 0; u < 4; u++) { acc2[u][0] = 0ull; acc2[u][1] = 0ull; }
        #pragma unroll
        for (int k = 0; k < 32; k++) {
            const float* qrow = &Qt2[k * 132 + 2 * ri];
            ull a0 = *(const ull*)&qrow[0];
            ull a1 = *(const ull*)&qrow[2];
            ull aa2 = *(const ull*)&qrow[4];
            ull a3 = *(const ull*)&qrow[6];
            float4 bv = *(const float4*)&Kt[k * 68 + tx * 4];
            ull b0 = ((const ull*)&bv)[0], b1 = ((const ull*)&bv)[1];
            FFMA2(acc2[0][0], a0, b0);  FFMA2(acc2[0][1], a0, b1);
            FFMA2(acc2[1][0], a1, b0);  FFMA2(acc2[1][1], a1, b1);
            FFMA2(acc2[2][0], aa2, b0); FFMA2(acc2[2][1], aa2, b1);
            FFMA2(acc2[3][0], a3, b0);  FFMA2(acc2[3][1], a3, b1);
        }

        int c0 = kc * 64 + tx * 4;
        #pragma unroll
        for (int u = 0; u < 4; u++) {
            int gi = i0 + ri + u;
            float mrow = stats_m[((size_t)(b * HH + h)) * NN + gi];
            float linv = 1.f / stats_l[((size_t)(b * HH + h)) * NN + gi];
            float2 pa = *(float2*)&acc2[u][0], pb = *(float2*)&acc2[u][1];
            float s[4] = {pa.x, pa.y, pb.x, pb.y};
            #pragma unroll
            for (int v = 0; v < 4; v++) {
                if (c0 + v <= gi)
                    macc[u][v] += __expf(s[v] * scale - mrow) * linv;
            }
        }
    }

    #pragma unroll
    for (int u = 0; u < 4; u++) {
        int gi = i0 + ri + u;
        float4 ov = make_float4(macc[u][0] * 0.125f, macc[u][1] * 0.125f,
                                macc[u][2] * 0.125f, macc[u][3] * 0.125f);
        *(float4*)&out[((size_t)(b * NN) + gi) * NN + kc * 64 + tx * 4] = ov;
    }
}

// ---------------- small kernels ----------------

__global__ void softmax_kernel(const float* __restrict__ src, float* __restrict__ dst, int L)
{
    size_t row = blockIdx.x;
    const float* p = src + row * (size_t)L;
    float* o = dst + row * (size_t)L;
    int t = threadIdx.x;
    float vals[8];
    int cnt = (L + 255) / 256;
    float mx = -1e30f;
    for (int i = 0; i < cnt; i++) {
        int idx = t + i * 256;
        vals[i] = (idx < L) ? p[idx] : -1e30f;
        mx = fmaxf(mx, vals[i]);
    }
    __shared__ float red[256];
    red[t] = mx; __syncthreads();
    for (int s = 128; s > 0; s >>= 1) { if (t < s) red[t] = fmaxf(red[t], red[t + s]); __syncthreads(); }
    mx = red[0]; __syncthreads();
    float sum = 0.f;
    for (int i = 0; i < cnt; i++) {
        int idx = t + i * 256;
        if (idx < L) { vals[i] = expf(vals[i] - mx); sum += vals[i]; }
    }
    red[t] = sum; __syncthreads();
    for (int s = 128; s > 0; s >>= 1) { if (t < s) red[t] += red[t + s]; __syncthreads(); }
    float inv = 1.f / red[0];
    for (int i = 0; i < cnt; i++) {
        int idx = t + i * 256;
        if (idx < L) o[idx] = vals[i] * inv;
    }
}

__global__ void add_ln_kernel(const float* __restrict__ a, const float* __restrict__ b,
                              const float* __restrict__ c,
                              const float* __restrict__ g, const float* __restrict__ bet,
                              float* __restrict__ out)
{
    size_t row = blockIdx.x;
    int t = threadIdx.x;
    float x = a[row * DD + t] + b[row * DD + t];
    if (c) x += c[row * DD + t];
    __shared__ float red[256];
    red[t] = x; __syncthreads();
    for (int s = 128; s > 0; s >>= 1) { if (t < s) red[t] += red[t + s]; __syncthreads(); }
    float mean = red[0] * (1.f / DD); __syncthreads();
    float d = x - mean;
    red[t] = d * d; __syncthreads();
    for (int s = 128; s > 0; s >>= 1) { if (t < s) red[t] += red[t + s]; __syncthreads(); }
    float var = red[0] * (1.f / DD);
    out[row * DD + t] = d * rsqrtf(var + 1e-5f) * g[t] + bet[t];
}

__global__ void embed_kernel(const int* __restrict__ q, const int* __restrict__ r,
                             const int* __restrict__ qry,
                             const float* __restrict__ M_emb, const float* __restrict__ E_emb,
                             const float* __restrict__ P,
                             float* __restrict__ M, float* __restrict__ E)
{
    int row = blockIdx.x; int t = threadIdx.x;
    int n = row % NN;
    int x = q[row] + NQ * r[row];
    M[(size_t)row * DD + t] = M_emb[(size_t)x * DD + t] + P[n * DD + t];
    E[(size_t)row * DD + t] = E_emb[(size_t)qry[row] * DD + t];
}

__global__ void gather_skill_kernel(const int* __restrict__ q, const float* __restrict__ rep,
                                    float* __restrict__ out)
{
    int row = blockIdx.x; int t = threadIdx.x;
    out[(size_t)row * DD + t] = rep[(size_t)q[row] * DD + t];
}

__global__ void gather_loc_kernel(const float* __restrict__ Sb, float* __restrict__ loc)
{
    int row = blockIdx.x; int t = threadIdx.x;
    int b = row / LWW, j = row % LWW;
    loc[(size_t)row * DD + t] = Sb[((size_t)(b * NN + NN - LWW + j)) * DD + t];
}

__global__ void sum5_kernel(const float* a, const float* b, const float* c,
                            const float* d, const float* e,
                            float* __restrict__ out, size_t n)
{
    size_t i = (size_t)blockIdx.x * 256 + threadIdx.x;
    if (i < n) out[i] = a[i] + b[i] + c[i] + d[i] + e[i];
}

__global__ void addloc_kernel(const float* __restrict__ locout, float* __restrict__ psum)
{
    int row = blockIdx.x; int t = threadIdx.x;
    int b = row / LWW, j = row % LWW;
    psum[((size_t)(b * NN + NN - LWW + j)) * DD + t] += locout[(size_t)row * DD + t];
}

__global__ void pred_kernel(const float* __restrict__ F, const float* __restrict__ w,
                            const float* __restrict__ b, float* __restrict__ out)
{
    size_t row = blockIdx.x;
    int t = threadIdx.x;
    float v = F[row * DD + t] * w[t];
    __shared__ float red[256];
    red[t] = v; __syncthreads();
    for (int s = 128; s > 0; s >>= 1) { if (t < s) red[t] += red[t + s]; __syncthreads(); }
    if (t == 0) out[row] = 1.f / (1.f + expf(-(red[0] + b[0])));
}

// ---------------- host orchestration ----------------

static void g128(const float* X, const float* W, const float* bias, float* Y,
                 int M, int K, int Nout, int act = 0,
                 int batch = 1, long long sX = 0, long long sW = 0, long long sY = 0)
{
    dim3 grid(Nout / 128, (M + 127) / 128, batch);
    mma_gemm<<<grid, 256>>>(X, W, bias, Y, M, K, Nout, act, sX, sW, sY);
}

static void run_attn(const float* Q, int sQ, const float* K, const float* V, int sKV,
                     float* O, float* sm_, float* sl_, int Lq, int Lk, int causal)
{
    dim3 grid((Lq + 63) / 64, BB * HH);
    attn_flash<<<grid, 128>>>(Q, sQ, K, V, sKV, O, sm_, sl_, Lq, Lk, causal);
}

#define GETSYM(var, symbol) float* var; { void* _p = nullptr; cudaGetSymbolAddress(&_p, symbol); var = (float*)_p; }

extern "C" void kernel_launch(void* const* d_in, const int* in_sizes, int n_in,
                              void* d_out, int out_size)
{
    const int*   q    = (const int*)d_in[0];
    const int*   r    = (const int*)d_in[1];
    const int*   qry  = (const int*)d_in[2];
    const float* M_emb = (const float*)d_in[3];
    const float* E_emb = (const float*)d_in[4];
    const float* P     = (const float*)d_in[5];
    const float* attn_in_w  = (const float*)d_in[6];
    const float* attn_in_b  = (const float*)d_in[7];
    const float* attn_out_w = (const float*)d_in[8];
    const float* attn_out_b = (const float*)d_in[9];
    const float* skill_cw   = (const float*)d_in[10];
    const float* skill_pw   = (const float*)d_in[11];
    const float* skill_pb   = (const float*)d_in[12];
    const float* skill_ew   = (const float*)d_in[13];
    const float* skill_eb   = (const float*)d_in[14];
    const float* ffn_w1 = (const float*)d_in[15];
    const float* ffn_b1 = (const float*)d_in[16];
    const float* ffn_w2 = (const float*)d_in[17];
    const float* ffn_b2 = (const float*)d_in[18];
    const float* ln1_g  = (const float*)d_in[19];
    const float* ln1_b  = (const float*)d_in[20];
    const float* ln2_g  = (const float*)d_in[21];
    const float* ln2_b  = (const float*)d_in[22];
    const float* pred_w = (const float*)d_in[23];
    const float* pred_b = (const float*)d_in[24];

    float* out_p = (float*)d_out;
    float* out_attn = out_p + BB * NN;

    GETSYM(pM, g_M);   GETSYM(pE, g_E);   GETSYM(pSbase, g_Sbase);
    GETSYM(pSsg, g_Ssg); GETSYM(pSglob, g_Sglob); GETSYM(pSbl, g_Sbl); GETSYM(pSsgl, g_Ssgl);
    GETSYM(pQKV, g_QKV); GETSYM(pQb, g_Qb); GETSYM(pKV, g_KV); GETSYM(pOh, g_Oh); GETSYM(pT, g_T);
    GETSYM(pSW, g_SW); GETSYM(psrep, g_srep); GETSYM(psgr, g_sgr);
    GETSYM(psg1, g_sg1); GETSYM(psg2, g_sg2);
    GETSYM(ploc, g_loc); GETSYM(plocout, g_locout);
    GETSYM(psum, g_sum); GETSYM(pf1, g_f1); GETSYM(pF, g_F);
    GETSYM(psm, g_sm); GETSYM(psl, g_sl);

    const size_t BND = (size_t)BB * NN * DD;
    const int MR = BB * NN;
    const int W3 = 3 * DD * DD, B3 = 3 * DD, W1 = DD * DD;

    // 1. embeddings
    embed_kernel<<<BB * NN, 256>>>(q, r, qry, M_emb, E_emb, P, pM, pE);

    // 2. attn0: q=E, kv=M, causal; flash saves per-row stats
    g128(pE, attn_in_w, attn_in_b, pQb, MR, DD, DD);
    g128(pM, attn_in_w + DD * DD, attn_in_b + DD, pKV, MR, DD, 2 * DD);
    run_attn(pQb, DD, pKV, pKV + DD, 2 * DD, pOh, psm, psl, NN, NN, 1);
    wmean_kernel<<<dim3(8, 32, 8), 256>>>(pQb, DD, pKV, 2 * DD, psm, psl, out_attn);
    g128(pOh, attn_out_w, attn_out_b, pT, MR, DD, DD);

    // 3. S_base = LN(attn0 + M + E)
    add_ln_kernel<<<BB * NN, 256>>>(pT, pM, pE, ln1_g, ln1_b, pSbase);

    // 4. local attention on last LW rows (output stays in plocout)
    gather_loc_kernel<<<BB * LWW, 256>>>(pSbase, ploc);
    g128(ploc, attn_in_w + 1 * W3, attn_in_b + 1 * B3, pQKV, BB * LWW, DD, 3 * DD);
    run_attn(pQKV, 3 * DD, pQKV + DD, pQKV + 2 * DD, 3 * DD, pOh, nullptr, nullptr, LWW, LWW, 1);
    g128(pOh, attn_out_w + 1 * W1, attn_out_b + 1 * DD, plocout, BB * LWW, DD, DD);

    // 5. skill path
    softmax_kernel<<<NQ, 256>>>(skill_cw, pSW, NQ);
    g128(pSW, skill_pw, skill_pb, psrep, NQ, NQ, DD);
    gather_skill_kernel<<<BB * NN, 256>>>(q, psrep, psgr);

    // 6. S_sg1[b] = S_base[b] @ sgr[b]^T
    g128(pSbase, psgr, nullptr, psg1, NN, DD, NN, 0, BB,
         (long long)NN * DD, (long long)NN * DD, (long long)NN * NN);

    // 7. S_sg2 = S_sg1 @ skill_to_embed_w^T + b
    g128(psg1, skill_ew, skill_eb, psg2, MR, NN, DD);

    // 8. attn2 (self, no mask) on S_sg2
    g128(psg2, attn_in_w + 2 * W3, attn_in_b + 2 * B3, pQKV, MR, DD, 3 * DD);
    run_attn(pQKV, 3 * DD, pQKV + DD, pQKV + 2 * DD, 3 * DD, pOh, nullptr, nullptr, NN, NN, 0);
    g128(pOh, attn_out_w + 2 * W1, attn_out_b + 2 * DD, pSsg, MR, DD, DD);

    // 9. attn3 (self, causal) on S_base
    g128(pSbase, attn_in_w + 3 * W3, attn_in_b + 3 * B3, pQKV, MR, DD, 3 * DD);
    run_attn(pQKV, 3 * DD, pQKV + DD, pQKV + 2 * DD, 3 * DD, pOh, nullptr, nullptr, NN, NN, 1);
    g128(pOh, attn_out_w + 3 * W1, attn_out_b + 3 * DD, pSglob, MR, DD, DD);

    // 10. attn4 analytic: q=S_base, kv=S_local (zeros except last LW rows)
    g128(pSbase, attn_in_w + 4 * W3, attn_in_b + 4 * B3, pQb, MR, DD, DD);
    g128(plocout, attn_in_w + 4 * W3 + DD * DD, attn_in_b + 4 * B3 + DD, pKV, BB * LWW, DD, 2 * DD);
    attn_bl_kernel<<<dim3(NN / 64, BB * HH), 64>>>(pQb, pKV, attn_in_b + 4 * B3, pOh);
    g128(pOh, attn_out_w + 4 * W1, attn_out_b + 4 * DD, pSbl, MR, DD, DD);

    // 11. attn5: q=S_sg, kv=S_glob, no mask
    g128(pSsg, attn_in_w + 5 * W3, attn_in_b + 5 * B3, pQb, MR, DD, DD);
    g128(pSglob, attn_in_w + 5 * W3 + DD * DD, attn_in_b + 5 * B3 + DD, pKV, MR, DD, 2 * DD);
    run_attn(pQb, DD, pKV, pKV + DD, 2 * DD, pOh, nullptr, nullptr, NN, NN, 0);
    g128(pOh, attn_out_w + 5 * W1, attn_out_b + 5 * DD, pSsgl, MR, DD, DD);

    // 12. S = Sbase + Ssg + Sglob + Sbl + Ssgl (+ S_local on last LW rows)
    sum5_kernel<<<(unsigned)((BND + 255) / 256), 256>>>(pSbase, pSsg, pSglob, pSbl, pSsgl,
                                                        psum, BND);
    addloc_kernel<<<BB * LWW, 256>>>(plocout, psum);

    // 13. FFN + residual + LN2
    g128(psum, ffn_w1, ffn_b1, pf1, MR, DD, DD, 1);
    g128(pf1, ffn_w2, ffn_b2, pT, MR, DD, DD);
    add_ln_kernel<<<BB * NN, 256>>>(pT, psum, nullptr, ln2_g, ln2_b, pF);

    // 14. prediction head
    pred_kernel<<<BB * NN, 256>>>(pF, pred_w, pred_b, out_p);
}

// round 7
// speedup vs baseline: 5.6969x; 1.3325x over previous
#include <cuda_runtime.h>
#include <math.h>
#include <stdint.h>

#define BB 32
#define NN 512
#define DD 256
#define HH 8
#define HD 32
#define LWW 25
#define NQ 2048

typedef unsigned long long ull;
#define FFMA2(d, a, b) asm("fma.rn.f32x2 %0, %1, %2, %3;" : "=l"(d) : "l"(a), "l"(b), "l"(d))
#define PACK2(d, s)    asm("mov.b64 %0, {%1, %1};" : "=l"(d) : "f"(s))

#define MMA_TF32(c, a0, a1, a2, a3, b0, b1) \
    asm volatile("mma.sync.aligned.m16n8k8.row.col.f32.tf32.tf32.f32 " \
        "{%0,%1,%2,%3}, {%4,%5,%6,%7}, {%8,%9}, {%0,%1,%2,%3};" \
        : "+f"((c)[0]), "+f"((c)[1]), "+f"((c)[2]), "+f"((c)[3]) \
        : "r"(a0), "r"(a1), "r"(a2), "r"(a3), "r"(b0), "r"(b1))

#define CP_ASYNC16(s, g, n) \
    asm volatile("cp.async.ca.shared.global [%0], [%1], 16, %2;" :: "r"(s), "l"(g), "r"(n) : "memory")
#define CP_COMMIT() asm volatile("cp.async.commit_group;" ::: "memory")
#define CP_WAIT1()  asm volatile("cp.async.wait_group 1;" ::: "memory")
#define CP_WAIT0()  asm volatile("cp.async.wait_group 0;" ::: "memory")

// ---------------- scratch ----------------
__device__ float g_M[BB*NN*DD];
__device__ float g_E[BB*NN*DD];
__device__ float g_Sbase[BB*NN*DD];
__device__ float g_Ssg[BB*NN*DD];
__device__ float g_Sglob[BB*NN*DD];
__device__ float g_Sbl[BB*NN*DD];
__device__ float g_Ssgl[BB*NN*DD];
__device__ float g_QKV[BB*NN*3*DD];
__device__ float g_Qb[BB*NN*DD];
__device__ float g_KV[BB*NN*2*DD];
__device__ float g_Oh[BB*NN*DD];
__device__ float g_T[BB*NN*DD];
__device__ float g_SW[NQ*NQ];
__device__ float g_srep[NQ*DD];
__device__ float g_sgr[BB*NN*DD];
__device__ float g_sg1[BB*NN*NN];
__device__ float g_sg2[BB*NN*DD];
__device__ float g_loc[BB*LWW*DD];
__device__ float g_locout[BB*LWW*DD];
__device__ float g_sum[BB*NN*DD];
__device__ float g_f1[BB*NN*DD];
__device__ float g_F[BB*NN*DD];
__device__ float g_sm[BB*HH*NN];
__device__ float g_sl[BB*HH*NN];

// ================= HMMA tf32 GEMM, cp.async double-buffered =================
// grid (Nout/128, ceil(M/128), batch), block 256 (8 warps = 2m x 4n).
// dyn smem = 2 bufs x (A 128x36 + B 128x36) floats = 73728 B.
__global__ __launch_bounds__(256) void mma_gemm(
    const float* __restrict__ X, const float* __restrict__ W,
    const float* __restrict__ bias, float* __restrict__ Y,
    int M, int K, int Nout, int act,
    long long sX, long long sW, long long sY)
{
    extern __shared__ float smem[];
    float* As = smem;              // [buf][128*36]
    float* Bs = smem + 2 * 4608;

    X += (size_t)blockIdx.z * sX;
    W += (size_t)blockIdx.z * sW;
    Y += (size_t)blockIdx.z * sY;

    int t = threadIdx.x, lane = t & 31, warp = t >> 5;
    int wm = warp & 1, wn = warp >> 1;
    int m0 = blockIdx.y * 128, n0 = blockIdx.x * 128;
    int mbase = wm * 64, nbase = wn * 32;
    int lq = lane >> 2, lr = lane & 3;

    uint32_t sbA = (uint32_t)__cvta_generic_to_shared(As);
    uint32_t sbB = (uint32_t)__cvta_generic_to_shared(Bs);

    int nch = K >> 5;

    // per-thread copy coords
    int cr[4], cc[4];
    #pragma unroll
    for (int l = 0; l < 4; l++) { int s = t + l * 256; cr[l] = s >> 3; cc[l] = (s & 7) * 4; }

    #define ISSUE(c) { \
        int buf = (c) & 1; \
        uint32_t offA = sbA + (uint32_t)(buf * 4608) * 4; \
        uint32_t offB = sbB + (uint32_t)(buf * 4608) * 4; \
        _Pragma("unroll") \
        for (int l = 0; l < 4; l++) { \
            int r = cr[l], c4 = cc[l]; \
            uint32_t ds = (uint32_t)(r * 36 + c4) * 4; \
            int gm = m0 + r; \
            const float* ga = (gm < M) ? &X[(size_t)gm * K + (c) * 32 + c4] : X; \
            CP_ASYNC16(offA + ds, ga, (gm < M) ? 16 : 0); \
            int gn = n0 + r; \
            const float* gb = (gn < Nout) ? &W[(size_t)gn * K + (c) * 32 + c4] : W; \
            CP_ASYNC16(offB + ds, gb, (gn < Nout) ? 16 : 0); \
        } \
        CP_COMMIT(); \
    }

    float acc[4][4][4];
    #pragma unroll
    for (int mi = 0; mi < 4; mi++)
        #pragma unroll
        for (int nj = 0; nj < 4; nj++)
            #pragma unroll
            for (int c = 0; c < 4; c++) acc[mi][nj][c] = 0.f;

    ISSUE(0);
    for (int c = 0; c < nch; c++) {
        if (c + 1 < nch) { ISSUE(c + 1); CP_WAIT1(); }
        else             { CP_WAIT0(); }
        __syncthreads();
        const float* Ab = As + (c & 1) * 4608;
        const float* Bb = Bs + (c & 1) * 4608;
        #pragma unroll
        for (int ks = 0; ks < 4; ks++) {
            int kk = ks * 8;
            uint32_t a[4][4], b[4][2];
            #pragma unroll
            for (int mi = 0; mi < 4; mi++) {
                int row = mbase + mi * 16 + lq;
                a[mi][0] = __float_as_uint(Ab[row * 36 + kk + lr]);
                a[mi][1] = __float_as_uint(Ab[(row + 8) * 36 + kk + lr]);
                a[mi][2] = __float_as_uint(Ab[row * 36 + kk + lr + 4]);
                a[mi][3] = __float_as_uint(Ab[(row + 8) * 36 + kk + lr + 4]);
            }
            #pragma unroll
            for (int nj = 0; nj < 4; nj++) {
                int nr = nbase + nj * 8 + lq;
                b[nj][0] = __float_as_uint(Bb[nr * 36 + kk + lr]);
                b[nj][1] = __float_as_uint(Bb[nr * 36 + kk + lr + 4]);
            }
            #pragma unroll
            for (int mi = 0; mi < 4; mi++)
                #pragma unroll
                for (int nj = 0; nj < 4; nj++)
                    MMA_TF32(acc[mi][nj], a[mi][0], a[mi][1], a[mi][2], a[mi][3],
                             b[nj][0], b[nj][1]);
        }
        __syncthreads();
    }

    #pragma unroll
    for (int nj = 0; nj < 4; nj++) {
        int col = n0 + nbase + nj * 8 + 2 * lr;
        float bx = 0.f, by = 0.f;
        if (bias) { bx = bias[col]; by = bias[col + 1]; }
        #pragma unroll
        for (int mi = 0; mi < 4; mi++) {
            int row = m0 + mbase + mi * 16 + lq;
            float v0 = acc[mi][nj][0] + bx, v1 = acc[mi][nj][1] + by;
            float v2 = acc[mi][nj][2] + bx, v3 = acc[mi][nj][3] + by;
            if (act == 1) {
                v0 = fmaxf(v0, 0.f); v1 = fmaxf(v1, 0.f);
                v2 = fmaxf(v2, 0.f); v3 = fmaxf(v3, 0.f);
            }
            if (row < M)     *(float2*)&Y[(size_t)row * Nout + col] = make_float2(v0, v1);
            if (row + 8 < M) *(float2*)&Y[(size_t)(row + 8) * Nout + col] = make_float2(v2, v3);
        }
    }
}

// ================= flash attention, tensor-core (raw fp32 bits as tf32) =================
__global__ __launch_bounds__(128) void attn_flash(
    const float* __restrict__ Qm, int sQ,
    const float* __restrict__ Km, const float* __restrict__ Vm, int sKV,
    float* __restrict__ O, float* __restrict__ stats_m, float* __restrict__ stats_l,
    int Lq, int Lk, int causal)
{
    __shared__ float Qs[64 * 36];
    __shared__ float Kt[32 * 72];
    __shared__ float Vs[64 * 40];
    __shared__ float Ps[64 * 68];

    int bh = blockIdx.y, b = bh >> 3, h = bh & 7;
    int i0 = blockIdx.x * 64;
    int t = threadIdx.x, lane = t & 31, warp = t >> 5;
    int lq = lane >> 2, lr = lane & 3;
    const float scale = 0.1767766953f;

    {
        int r = t & 63, half = t >> 6;
        int gi = i0 + r;
        float buf[16];
        #pragma unroll
        for (int i = 0; i < 16; i++) buf[i] = 0.f;
        if (gi < Lq) {
            const float* qp = &Qm[(size_t)(b * Lq + gi) * sQ + h * HD + half * 16];
            #pragma unroll
            for (int i = 0; i < 4; i++)
                *(float4*)&buf[i * 4] = *(const float4*)&qp[i * 4];
        }
        #pragma unroll
        for (int i = 0; i < 16; i++)
            Qs[r * 36 + half * 16 + i] = buf[i];
    }

    float m0 = -1e30f, m1 = -1e30f, l0 = 0.f, l1 = 0.f;
    float o[4][4];
    #pragma unroll
    for (int i = 0; i < 4; i++)
        #pragma unroll
        for (int j = 0; j < 4; j++) o[i][j] = 0.f;

    int gi0 = i0 + warp * 16 + lq, gi1 = gi0 + 8;
    int nkc = (Lk + 63) >> 6;
    if (causal) { int mx = (i0 >> 6) + 1; if (mx < nkc) nkc = mx; }

    for (int kc = 0; kc < nkc; kc++) {
        __syncthreads();
        {
            int key = t & 63, half = t >> 6;
            int gj = kc * 64 + key;
            float kb[16], vb[16];
            #pragma unroll
            for (int i = 0; i < 16; i++) { kb[i] = 0.f; vb[i] = 0.f; }
            if (gj < Lk) {
                const float* kp = &Km[(size_t)(b * Lk + gj) * sKV + h * HD + half * 16];
                const float* vp = &Vm[(size_t)(b * Lk + gj) * sKV + h * HD + half * 16];
                #pragma unroll
                for (int i = 0; i < 4; i++) {
                    *(float4*)&kb[i * 4] = *(const float4*)&kp[i * 4];
                    *(float4*)&vb[i * 4] = *(const float4*)&vp[i * 4];
                }
            }
            #pragma unroll
            for (int i = 0; i < 16; i++) {
                Kt[(half * 16 + i) * 72 + key] = kb[i];
                Vs[key * 40 + half * 16 + i] = vb[i];
            }
        }
        __syncthreads();

        uint32_t a[4][4];
        #pragma unroll
        for (int ks = 0; ks < 4; ks++) {
            int rb = (warp * 16 + lq) * 36 + ks * 8;
            a[ks][0] = __float_as_uint(Qs[rb + lr]);
            a[ks][1] = __float_as_uint(Qs[rb + 8 * 36 + lr]);
            a[ks][2] = __float_as_uint(Qs[rb + lr + 4]);
            a[ks][3] = __float_as_uint(Qs[rb + 8 * 36 + lr + 4]);
        }
        float sc[8][4];
        #pragma unroll
        for (int nt = 0; nt < 8; nt++) {
            #pragma unroll
            for (int c = 0; c < 4; c++) sc[nt][c] = 0.f;
            #pragma unroll
            for (int ks = 0; ks < 4; ks++) {
                uint32_t b0 = __float_as_uint(Kt[(ks * 8 + lr) * 72 + nt * 8 + lq]);
                uint32_t b1 = __float_as_uint(Kt[(ks * 8 + lr + 4) * 72 + nt * 8 + lq]);
                MMA_TF32(sc[nt], a[ks][0], a[ks][1], a[ks][2], a[ks][3], b0, b1);
            }
        }

        float r0mx = -1e30f, r1mx = -1e30f;
        #pragma unroll
        for (int nt = 0; nt < 8; nt++) {
            int c0 = kc * 64 + nt * 8 + lr * 2;
            float s0 = sc[nt][0] * scale, s1 = sc[nt][1] * scale;
            float s2 = sc[nt][2] * scale, s3 = sc[nt][3] * scale;
            if (c0 + 0 >= Lk || (causal && c0 + 0 > gi0)) s0 = -1e30f;
            if (c0 + 1 >= Lk || (causal && c0 + 1 > gi0)) s1 = -1e30f;
            if (c0 + 0 >= Lk || (causal && c0 + 0 > gi1)) s2 = -1e30f;
            if (c0 + 1 >= Lk || (causal && c0 + 1 > gi1)) s3 = -1e30f;
            sc[nt][0] = s0; sc[nt][1] = s1; sc[nt][2] = s2; sc[nt][3] = s3;
            r0mx = fmaxf(r0mx, fmaxf(s0, s1));
            r1mx = fmaxf(r1mx, fmaxf(s2, s3));
        }
        #pragma unroll
        for (int off = 1; off < 4; off <<= 1) {
            r0mx = fmaxf(r0mx, __shfl_xor_sync(0xffffffffu, r0mx, off));
            r1mx = fmaxf(r1mx, __shfl_xor_sync(0xffffffffu, r1mx, off));
        }
        float mn0 = fmaxf(m0, r0mx), mn1 = fmaxf(m1, r1mx);
        float alpha0 = __expf(m0 - mn0), alpha1 = __expf(m1 - mn1);
        float rs0 = 0.f, rs1 = 0.f;
        #pragma unroll
        for (int nt = 0; nt < 8; nt++) {
            float p0 = __expf(sc[nt][0] - mn0), p1 = __expf(sc[nt][1] - mn0);
            float p2 = __expf(sc[nt][2] - mn1), p3 = __expf(sc[nt][3] - mn1);
            rs0 += p0 + p1; rs1 += p2 + p3;
            *(float2*)&Ps[(warp * 16 + lq) * 68 + nt * 8 + lr * 2] = make_float2(p0, p1);
            *(float2*)&Ps[(warp * 16 + lq + 8) * 68 + nt * 8 + lr * 2] = make_float2(p2, p3);
        }
        #pragma unroll
        for (int off = 1; off < 4; off <<= 1) {
            rs0 += __shfl_xor_sync(0xffffffffu, rs0, off);
            rs1 += __shfl_xor_sync(0xffffffffu, rs1, off);
        }
        l0 = l0 * alpha0 + rs0; l1 = l1 * alpha1 + rs1;
        m0 = mn0; m1 = mn1;
        #pragma unroll
        for (int nt2 = 0; nt2 < 4; nt2++) {
            o[nt2][0] *= alpha0; o[nt2][1] *= alpha0;
            o[nt2][2] *= alpha1; o[nt2][3] *= alpha1;
        }
        __syncwarp();

        #pragma unroll
        for (int ks = 0; ks < 8; ks++) {
            int rb = (warp * 16 + lq) * 68 + ks * 8;
            uint32_t pa0 = __float_as_uint(Ps[rb + lr]);
            uint32_t pa1 = __float_as_uint(Ps[rb + 8 * 68 + lr]);
            uint32_t pa2 = __float_as_uint(Ps[rb + lr + 4]);
            uint32_t pa3 = __float_as_uint(Ps[rb + 8 * 68 + lr + 4]);
            #pragma unroll
            for (int nt2 = 0; nt2 < 4; nt2++) {
                uint32_t b0 = __float_as_uint(Vs[(ks * 8 + lr) * 40 + nt2 * 8 + lq]);
                uint32_t b1 = __float_as_uint(Vs[(ks * 8 + lr + 4) * 40 + nt2 * 8 + lq]);
                MMA_TF32(o[nt2], pa0, pa1, pa2, pa3, b0, b1);
            }
        }
        __syncwarp();
    }

    float inv0 = 1.f / l0, inv1 = 1.f / l1;
    if (gi0 < Lq) {
        float* orow = &O[(size_t)(b * Lq + gi0) * DD + h * HD];
        #pragma unroll
        for (int nt2 = 0; nt2 < 4; nt2++)
            *(float2*)&orow[nt2 * 8 + lr * 2] = make_float2(o[nt2][0] * inv0, o[nt2][1] * inv0);
        if (stats_m && lr == 0) {
            stats_m[(size_t)bh * Lq + gi0] = m0;
            stats_l[(size_t)bh * Lq + gi0] = l0;
        }
    }
    if (gi1 < Lq) {
        float* orow = &O[(size_t)(b * Lq + gi1) * DD + h * HD];
        #pragma unroll
        for (int nt2 = 0; nt2 < 4; nt2++)
            *(float2*)&orow[nt2 * 8 + lr * 2] = make_float2(o[nt2][2] * inv1, o[nt2][3] * inv1);
        if (stats_m && lr == 0) {
            stats_m[(size_t)bh * Lq + gi1] = m1;
            stats_l[(size_t)bh * Lq + gi1] = l1;
        }
    }
}

// ================= attn4 analytic (unchanged) =================
__global__ __launch_bounds__(64) void attn_bl_kernel(
    const float* __restrict__ Qm,
    const float* __restrict__ KVloc,
    const float* __restrict__ inb,
    float* __restrict__ O)
{
    __shared__ float Ks[LWW][HD + 1], Vsm[LWW][HD + 1], kb[HD], vb[HD];
    int bh = blockIdx.y, b = bh >> 3, h = bh & 7;
    int i0 = blockIdx.x * 64;
    int t = threadIdx.x;
    const float scale = 0.1767766953f;

    for (int i = t; i < LWW * HD; i += 64) {
        int rr = i / HD, dd = i % HD;
        Ks[rr][dd]  = KVloc[(size_t)(b * LWW + rr) * 512 + h * HD + dd];
        Vsm[rr][dd] = KVloc[(size_t)(b * LWW + rr) * 512 + 256 + h * HD + dd];
    }
    if (t < HD) { kb[t] = inb[DD + h * HD + t]; vb[t] = inb[2 * DD + h * HD + t]; }
    __syncthreads();

    int gi = i0 + t;
    float qv[HD];
    const float* qp = &Qm[(size_t)(b * NN + gi) * DD + h * HD];
    #pragma unroll
    for (int d = 0; d < HD; d++) qv[d] = qp[d];

    float s0 = 0.f;
    #pragma unroll
    for (int d = 0; d < HD; d++) s0 = fmaf(qv[d], kb[d], s0);
    s0 *= scale;
    float s[LWW];
    float mx = s0;
    #pragma unroll
    for (int j = 0; j < LWW; j++) {
        float acc = 0.f;
        #pragma unroll
        for (int d = 0; d < HD; d++) acc = fmaf(qv[d], Ks[j][d], acc);
        s[j] = acc * scale;
        mx = fmaxf(mx, s[j]);
    }
    float e0 = __expf(s0 - mx) * (float)(NN - LWW);
    float denom = e0;
    float ov[HD];
    #pragma unroll
    for (int d = 0; d < HD; d++) ov[d] = e0 * vb[d];
    #pragma unroll
    for (int j = 0; j < LWW; j++) {
        float ej = __expf(s[j] - mx);
        denom += ej;
        #pragma unroll
        for (int d = 0; d < HD; d++) ov[d] = fmaf(ej, Vsm[j][d], ov[d]);
    }
    float inv = 1.f / denom;
    float* orow = &O[(size_t)(b * NN + gi) * DD + h * HD];
    #pragma unroll
    for (int d = 0; d < HD; d++) orow[d] = ov[d] * inv;
}

// ---------------- wmean pass2 (unchanged) ----------------
__global__ __launch_bounds__(256) void wmean_kernel(
    const float* __restrict__ Qm, int sQ,
    const float* __restrict__ Km, int sKV,
    const float* __restrict__ stats_m, const float* __restrict__ stats_l,
    float* __restrict__ out)
{
    __shared__ float Qt2[32 * 132];
    __shared__ float Kt[32 * 68];

    int qt = blockIdx.x, b = blockIdx.y, kc = blockIdx.z;
    int i0 = qt * 64;
    int t = threadIdx.x;
    int ty = t >> 4, tx = t & 15;
    int ri = ty * 4;
    const float scale = 0.1767766953f;

    float macc[4][4];
    #pragma unroll
    for (int u = 0; u < 4; u++)
        #pragma unroll
        for (int v = 0; v < 4; v++) macc[u][v] = 0.f;

    for (int h = 0; h < HH; h++) {
        __syncthreads();
        {
            int r = t >> 2, k8 = (t & 3) * 8;
            int gi = i0 + r;
            const float* qp = &Qm[(size_t)(b * NN + gi) * sQ + h * HD + k8];
            float4 v0 = *(const float4*)qp, v1 = *(const float4*)(qp + 4);
            float vv[8] = {v0.x, v0.y, v0.z, v0.w, v1.x, v1.y, v1.z, v1.w};
            #pragma unroll
            for (int kk = 0; kk < 8; kk++)
                *(float2*)&Qt2[(k8 + kk) * 132 + 2 * r] = make_float2(vv[kk], vv[kk]);
            int gj = kc * 64 + r;
            const float* kp = &Km[(size_t)(b * NN + gj) * sKV + h * HD + k8];
            float4 w0 = *(const float4*)kp, w1 = *(const float4*)(kp + 4);
            float ww[8] = {w0.x, w0.y, w0.z, w0.w, w1.x, w1.y, w1.z, w1.w};
            #pragma unroll
            for (int kk = 0; kk < 8; kk++) Kt[(k8 + kk) * 68 + r] = ww[kk];
        }
        __syncthreads();

        ull acc2[4][2];
        #pragma unroll
        for (int u = 0; u < 4; u++) { acc2[u][0] = 0ull; acc2[u][1] = 0ull; }
        #pragma unroll
        for (int k = 0; k < 32; k++) {
            const float* qrow = &Qt2[k * 132 + 2 * ri];
            ull a0 = *(const ull*)&qrow[0];
            ull a1 = *(const ull*)&qrow[2];
            ull aa2 = *(const ull*)&qrow[4];
            ull a3 = *(const ull*)&qrow[6];
            float4 bv = *(const float4*)&Kt[k * 68 + tx * 4];
            ull b0 = ((const ull*)&bv)[0], b1 = ((const ull*)&bv)[1];
            FFMA2(acc2[0][0], a0, b0);  FFMA2(acc2[0][1], a0, b1);
            FFMA2(acc2[1][0], a1, b0);  FFMA2(acc2[1][1], a1, b1);
            FFMA2(acc2[2][0], aa2, b0); FFMA2(acc2[2][1], aa2, b1);
            FFMA2(acc2[3][0], a3, b0);  FFMA2(acc2[3][1], a3, b1);
        }

        int c0 = kc * 64 + tx * 4;
        #pragma unroll
        for (int u = 0; u < 4; u++) {
            int gi = i0 + ri + u;
            float mrow = stats_m[((size_t)(b * HH + h)) * NN + gi];
            float linv = 1.f / stats_l[((size_t)(b * HH + h)) * NN + gi];
            float2 pa = *(float2*)&acc2[u][0], pb = *(float2*)&acc2[u][1];
            float s[4] = {pa.x, pa.y, pb.x, pb.y};
            #pragma unroll
            for (int v = 0; v < 4; v++) {
                if (c0 + v <= gi)
                    macc[u][v] += __expf(s[v] * scale - mrow) * linv;
            }
        }
    }

    #pragma unroll
    for (int u = 0; u < 4; u++) {
        int gi = i0 + ri + u;
        float4 ov = make_float4(macc[u][0] * 0.125f, macc[u][1] * 0.125f,
                                macc[u][2] * 0.125f, macc[u][3] * 0.125f);
        *(float4*)&out[((size_t)(b * NN) + gi) * NN + kc * 64 + tx * 4] = ov;
    }
}

// ---------------- small kernels ----------------

__global__ void softmax_kernel(const float* __restrict__ src, float* __restrict__ dst, int L)
{
    size_t row = blockIdx.x;
    const float* p = src + row * (size_t)L;
    float* o = dst + row * (size_t)L;
    int t = threadIdx.x;
    float vals[8];
    int cnt = (L + 255) / 256;
    float mx = -1e30f;
    for (int i = 0; i < cnt; i++) {
        int idx = t + i * 256;
        vals[i] = (idx < L) ? p[idx] : -1e30f;
        mx = fmaxf(mx, vals[i]);
    }
    __shared__ float red[256];
    red[t] = mx; __syncthreads();
    for (int s = 128; s > 0; s >>= 1) { if (t < s) red[t] = fmaxf(red[t], red[t + s]); __syncthreads(); }
    mx = red[0]; __syncthreads();
    float sum = 0.f;
    for (int i = 0; i < cnt; i++) {
        int idx = t + i * 256;
        if (idx < L) { vals[i] = expf(vals[i] - mx); sum += vals[i]; }
    }
    red[t] = sum; __syncthreads();
    for (int s = 128; s > 0; s >>= 1) { if (t < s) red[t] += red[t + s]; __syncthreads(); }
    float inv = 1.f / red[0];
    for (int i = 0; i < cnt; i++) {
        int idx = t + i * 256;
        if (idx < L) o[idx] = vals[i] * inv;
    }
}

__global__ void add_ln_kernel(const float* __restrict__ a, const float* __restrict__ b,
                              const float* __restrict__ c,
                              const float* __restrict__ g, const float* __restrict__ bet,
                              float* __restrict__ out)
{
    size_t row = blockIdx.x;
    int t = threadIdx.x;
    float x = a[row * DD + t] + b[row * DD + t];
    if (c) x += c[row * DD + t];
    __shared__ float red[256];
    red[t] = x; __syncthreads();
    for (int s = 128; s > 0; s >>= 1) { if (t < s) red[t] += red[t + s]; __syncthreads(); }
    float mean = red[0] * (1.f / DD); __syncthreads();
    float d = x - mean;
    red[t] = d * d; __syncthreads();
    for (int s = 128; s > 0; s >>= 1) { if (t < s) red[t] += red[t + s]; __syncthreads(); }
    float var = red[0] * (1.f / DD);
    out[row * DD + t] = d * rsqrtf(var + 1e-5f) * g[t] + bet[t];
}

__global__ void embed_kernel(const int* __restrict__ q, const int* __restrict__ r,
                             const int* __restrict__ qry,
                             const float* __restrict__ M_emb, const float* __restrict__ E_emb,
                             const float* __restrict__ P,
                             float* __restrict__ M, float* __restrict__ E)
{
    int row = blockIdx.x; int t = threadIdx.x;
    int n = row % NN;
    int x = q[row] + NQ * r[row];
    M[(size_t)row * DD + t] = M_emb[(size_t)x * DD + t] + P[n * DD + t];
    E[(size_t)row * DD + t] = E_emb[(size_t)qry[row] * DD + t];
}

__global__ void gather_skill_kernel(const int* __restrict__ q, const float* __restrict__ rep,
                                    float* __restrict__ out)
{
    int row = blockIdx.x; int t = threadIdx.x;
    out[(size_t)row * DD + t] = rep[(size_t)q[row] * DD + t];
}

__global__ void gather_loc_kernel(const float* __restrict__ Sb, float* __restrict__ loc)
{
    int row = blockIdx.x; int t = threadIdx.x;
    int b = row / LWW, j = row % LWW;
    loc[(size_t)row * DD + t] = Sb[((size_t)(b * NN + NN - LWW + j)) * DD + t];
}

__global__ void sum5_kernel(const float* a, const float* b, const float* c,
                            const float* d, const float* e,
                            float* __restrict__ out, size_t n)
{
    size_t i = (size_t)blockIdx.x * 256 + threadIdx.x;
    if (i < n) out[i] = a[i] + b[i] + c[i] + d[i] + e[i];
}

__global__ void addloc_kernel(const float* __restrict__ locout, float* __restrict__ psum)
{
    int row = blockIdx.x; int t = threadIdx.x;
    int b = row / LWW, j = row % LWW;
    psum[((size_t)(b * NN + NN - LWW + j)) * DD + t] += locout[(size_t)row * DD + t];
}

__global__ void pred_kernel(const float* __restrict__ F, const float* __restrict__ w,
                            const float* __restrict__ b, float* __restrict__ out)
{
    size_t row = blockIdx.x;
    int t = threadIdx.x;
    float v = F[row * DD + t] * w[t];
    __shared__ float red[256];
    red[t] = v; __syncthreads();
    for (int s = 128; s > 0; s >>= 1) { if (t < s) red[t] += red[t + s]; __syncthreads(); }
    if (t == 0) out[row] = 1.f / (1.f + expf(-(red[0] + b[0])));
}

// ---------------- host orchestration ----------------

static void g128(const float* X, const float* W, const float* bias, float* Y,
                 int M, int K, int Nout, int act = 0,
                 int batch = 1, long long sX = 0, long long sW = 0, long long sY = 0)
{
    static bool attr_set = false;
    if (!attr_set) {
        cudaFuncSetAttribute(mma_gemm, cudaFuncAttributeMaxDynamicSharedMemorySize, 73728);
        attr_set = true;
    }
    dim3 grid(Nout / 128, (M + 127) / 128, batch);
    mma_gemm<<<grid, 256, 73728>>>(X, W, bias, Y, M, K, Nout, act, sX, sW, sY);
}

static void run_attn(const float* Q, int sQ, const float* K, const float* V, int sKV,
                     float* O, float* sm_, float* sl_, int Lq, int Lk, int causal)
{
    dim3 grid((Lq + 63) / 64, BB * HH);
    attn_flash<<<grid, 128>>>(Q, sQ, K, V, sKV, O, sm_, sl_, Lq, Lk, causal);
}

#define GETSYM(var, symbol) float* var; { void* _p = nullptr; cudaGetSymbolAddress(&_p, symbol); var = (float*)_p; }

extern "C" void kernel_launch(void* const* d_in, const int* in_sizes, int n_in,
                              void* d_out, int out_size)
{
    const int*   q    = (const int*)d_in[0];
    const int*   r    = (const int*)d_in[1];
    const int*   qry  = (const int*)d_in[2];
    const float* M_emb = (const float*)d_in[3];
    const float* E_emb = (const float*)d_in[4];
    const float* P     = (const float*)d_in[5];
    const float* attn_in_w  = (const float*)d_in[6];
    const float* attn_in_b  = (const float*)d_in[7];
    const float* attn_out_w = (const float*)d_in[8];
    const float* attn_out_b = (const float*)d_in[9];
    const float* skill_cw   = (const float*)d_in[10];
    const float* skill_pw   = (const float*)d_in[11];
    const float* skill_pb   = (const float*)d_in[12];
    const float* skill_ew   = (const float*)d_in[13];
    const float* skill_eb   = (const float*)d_in[14];
    const float* ffn_w1 = (const float*)d_in[15];
    const float* ffn_b1 = (const float*)d_in[16];
    const float* ffn_w2 = (const float*)d_in[17];
    const float* ffn_b2 = (const float*)d_in[18];
    const float* ln1_g  = (const float*)d_in[19];
    const float* ln1_b  = (const float*)d_in[20];
    const float* ln2_g  = (const float*)d_in[21];
    const float* ln2_b  = (const float*)d_in[22];
    const float* pred_w = (const float*)d_in[23];
    const float* pred_b = (const float*)d_in[24];

    float* out_p = (float*)d_out;
    float* out_attn = out_p + BB * NN;

    GETSYM(pM, g_M);   GETSYM(pE, g_E);   GETSYM(pSbase, g_Sbase);
    GETSYM(pSsg, g_Ssg); GETSYM(pSglob, g_Sglob); GETSYM(pSbl, g_Sbl); GETSYM(pSsgl, g_Ssgl);
    GETSYM(pQKV, g_QKV); GETSYM(pQb, g_Qb); GETSYM(pKV, g_KV); GETSYM(pOh, g_Oh); GETSYM(pT, g_T);
    GETSYM(pSW, g_SW); GETSYM(psrep, g_srep); GETSYM(psgr, g_sgr);
    GETSYM(psg1, g_sg1); GETSYM(psg2, g_sg2);
    GETSYM(ploc, g_loc); GETSYM(plocout, g_locout);
    GETSYM(psum, g_sum); GETSYM(pf1, g_f1); GETSYM(pF, g_F);
    GETSYM(psm, g_sm); GETSYM(psl, g_sl);

    const size_t BND = (size_t)BB * NN * DD;
    const int MR = BB * NN;
    const int W3 = 3 * DD * DD, B3 = 3 * DD, W1 = DD * DD;

    // 1. embeddings
    embed_kernel<<<BB * NN, 256>>>(q, r, qry, M_emb, E_emb, P, pM, pE);

    // 2. attn0: q=E, kv=M, causal; flash saves per-row stats
    g128(pE, attn_in_w, attn_in_b, pQb, MR, DD, DD);
    g128(pM, attn_in_w + DD * DD, attn_in_b + DD, pKV, MR, DD, 2 * DD);
    run_attn(pQb, DD, pKV, pKV + DD, 2 * DD, pOh, psm, psl, NN, NN, 1);
    wmean_kernel<<<dim3(8, 32, 8), 256>>>(pQb, DD, pKV, 2 * DD, psm, psl, out_attn);
    g128(pOh, attn_out_w, attn_out_b, pT, MR, DD, DD);

    // 3. S_base = LN(attn0 + M + E)
    add_ln_kernel<<<BB * NN, 256>>>(pT, pM, pE, ln1_g, ln1_b, pSbase);

    // 4. local attention on last LW rows (output stays in plocout)
    gather_loc_kernel<<<BB * LWW, 256>>>(pSbase, ploc);
    g128(ploc, attn_in_w + 1 * W3, attn_in_b + 1 * B3, pQKV, BB * LWW, DD, 3 * DD);
    run_attn(pQKV, 3 * DD, pQKV + DD, pQKV + 2 * DD, 3 * DD, pOh, nullptr, nullptr, LWW, LWW, 1);
    g128(pOh, attn_out_w + 1 * W1, attn_out_b + 1 * DD, plocout, BB * LWW, DD, DD);

    // 5. skill path
    softmax_kernel<<<NQ, 256>>>(skill_cw, pSW, NQ);
    g128(pSW, skill_pw, skill_pb, psrep, NQ, NQ, DD);
    gather_skill_kernel<<<BB * NN, 256>>>(q, psrep, psgr);

    // 6. S_sg1[b] = S_base[b] @ sgr[b]^T
    g128(pSbase, psgr, nullptr, psg1, NN, DD, NN, 0, BB,
         (long long)NN * DD, (long long)NN * DD, (long long)NN * NN);

    // 7. S_sg2 = S_sg1 @ skill_to_embed_w^T + b
    g128(psg1, skill_ew, skill_eb, psg2, MR, NN, DD);

    // 8. attn2 (self, no mask) on S_sg2
    g128(psg2, attn_in_w + 2 * W3, attn_in_b + 2 * B3, pQKV, MR, DD, 3 * DD);
    run_attn(pQKV, 3 * DD, pQKV + DD, pQKV + 2 * DD, 3 * DD, pOh, nullptr, nullptr, NN, NN, 0);
    g128(pOh, attn_out_w + 2 * W1, attn_out_b + 2 * DD, pSsg, MR, DD, DD);

    // 9. attn3 (self, causal) on S_base
    g128(pSbase, attn_in_w + 3 * W3, attn_in_b + 3 * B3, pQKV, MR, DD, 3 * DD);
    run_attn(pQKV, 3 * DD, pQKV + DD, pQKV + 2 * DD, 3 * DD, pOh, nullptr, nullptr, NN, NN, 1);
    g128(pOh, attn_out_w + 3 * W1, attn_out_b + 3 * DD, pSglob, MR, DD, DD);

    // 10. attn4 analytic: q=S_base, kv=S_local (zeros except last LW rows)
    g128(pSbase, attn_in_w + 4 * W3, attn_in_b + 4 * B3, pQb, MR, DD, DD);
    g128(plocout, attn_in_w + 4 * W3 + DD * DD, attn_in_b + 4 * B3 + DD, pKV, BB * LWW, DD, 2 * DD);
    attn_bl_kernel<<<dim3(NN / 64, BB * HH), 64>>>(pQb, pKV, attn_in_b + 4 * B3, pOh);
    g128(pOh, attn_out_w + 4 * W1, attn_out_b + 4 * DD, pSbl, MR, DD, DD);

    // 11. attn5: q=S_sg, kv=S_glob, no mask
    g128(pSsg, attn_in_w + 5 * W3, attn_in_b + 5 * B3, pQb, MR, DD, DD);
    g128(pSglob, attn_in_w + 5 * W3 + DD * DD, attn_in_b + 5 * B3 + DD, pKV, MR, DD, 2 * DD);
    run_attn(pQb, DD, pKV, pKV + DD, 2 * DD, pOh, nullptr, nullptr, NN, NN, 0);
    g128(pOh, attn_out_w + 5 * W1, attn_out_b + 5 * DD, pSsgl, MR, DD, DD);

    // 12. S = Sbase + Ssg + Sglob + Sbl + Ssgl (+ S_local on last LW rows)
    sum5_kernel<<<(unsigned)((BND + 255) / 256), 256>>>(pSbase, pSsg, pSglob, pSbl, pSsgl,
                                                        psum, BND);
    addloc_kernel<<<BB * LWW, 256>>>(plocout, psum);

    // 13. FFN + residual + LN2
    g128(psum, ffn_w1, ffn_b1, pf1, MR, DD, DD, 1);
    g128(pf1, ffn_w2, ffn_b2, pT, MR, DD, DD);
    add_ln_kernel<<<BB * NN, 256>>>(pT, psum, nullptr, ln2_g, ln2_b, pF);

    // 14. prediction head
    pred_kernel<<<BB * NN, 256>>>(pF, pred_w, pred_b, out_p);
}